// round 1
// baseline (speedup 1.0000x reference)
#include <cuda_runtime.h>
#include <cuda_bf16.h>
#include <math.h>

// ---------------------------------------------------------------------------
// Problem constants
// ---------------------------------------------------------------------------
#define BATCH   8
#define HW      32
#define L_SEQ   1024          // 32*32
#define DIM     384
#define DI      768           // D_INNER
#define DS      16            // D_STATE
#define XZW     1536          // 2*D_INNER
#define NTOK    (BATCH*L_SEQ) // 8192

// ---------------------------------------------------------------------------
// Scratch (device globals -- no allocation allowed in kernel_launch)
// ---------------------------------------------------------------------------
__device__ float g_xn   [NTOK*DIM];   // layernorm output
__device__ float g_seq  [NTOK*DIM];   // gathered (maybe transposed) sequence
__device__ float g_xg   [NTOK];       // per-pixel channel mean of xn
__device__ int   g_isv  [BATCH];      // is_vert flag per batch
__device__ float g_xz   [NTOK*XZW];   // in_proj output
__device__ float g_xc   [NTOK*DI];    // conv+silu output
__device__ float g_delta[NTOK*DI];    // softplus(dt) output
__device__ float g_bc   [NTOK*2*DS];  // x_proj output (B then C)
__device__ float g_y    [NTOK*DI];    // scan output (gated)

// ---------------------------------------------------------------------------
// Helpers
// ---------------------------------------------------------------------------
__device__ __forceinline__ float ex2_approx(float x) {
    float r;
    asm("ex2.approx.f32 %0, %1;" : "=f"(r) : "f"(x));
    return r;
}
__device__ __forceinline__ float softplusf(float x) {
    return fmaxf(x, 0.f) + log1pf(__expf(-fabsf(x)));
}
__device__ __forceinline__ float siluf(float x) {
    return x / (1.f + __expf(-x));
}
__device__ __forceinline__ int refl(int v) {
    return v < 0 ? -v : (v > 31 ? 62 - v : v);
}

// ---------------------------------------------------------------------------
// 1) LayerNorm: warp per token, also emits channel-mean image g_xg
// ---------------------------------------------------------------------------
__global__ __launch_bounds__(256) void ln_kernel(
    const float* __restrict__ x, const float* __restrict__ gam,
    const float* __restrict__ bet, float* __restrict__ xn,
    float* __restrict__ xgm)
{
    int warp = threadIdx.x >> 5, lane = threadIdx.x & 31;
    int r = blockIdx.x * 8 + warp;
    const float4* xp = (const float4*)(x + (size_t)r * DIM);
    float4 v[3];
    float s = 0.f, s2 = 0.f;
#pragma unroll
    for (int i = 0; i < 3; i++) {
        v[i] = xp[lane + 32 * i];
        s  += v[i].x + v[i].y + v[i].z + v[i].w;
        s2 += v[i].x * v[i].x + v[i].y * v[i].y + v[i].z * v[i].z + v[i].w * v[i].w;
    }
#pragma unroll
    for (int o = 16; o; o >>= 1) {
        s  += __shfl_xor_sync(0xffffffffu, s,  o);
        s2 += __shfl_xor_sync(0xffffffffu, s2, o);
    }
    float mu   = s * (1.f / DIM);
    float var  = s2 * (1.f / DIM) - mu * mu;
    float rstd = rsqrtf(var + 1e-5f);

    float xs = 0.f;
    float4* op = (float4*)(xn + (size_t)r * DIM);
    const float4* gp = (const float4*)gam;
    const float4* bp = (const float4*)bet;
#pragma unroll
    for (int i = 0; i < 3; i++) {
        float4 g4 = gp[lane + 32 * i];
        float4 b4 = bp[lane + 32 * i];
        float4 o4;
        o4.x = (v[i].x - mu) * rstd * g4.x + b4.x;
        o4.y = (v[i].y - mu) * rstd * g4.y + b4.y;
        o4.z = (v[i].z - mu) * rstd * g4.z + b4.z;
        o4.w = (v[i].w - mu) * rstd * g4.w + b4.w;
        xs += o4.x + o4.y + o4.z + o4.w;
        op[lane + 32 * i] = o4;
    }
#pragma unroll
    for (int o = 16; o; o >>= 1) xs += __shfl_xor_sync(0xffffffffu, xs, o);
    if (lane == 0) xgm[r] = xs * (1.f / DIM);
}

// ---------------------------------------------------------------------------
// 2) Direction selection: one block per batch (gradients + antialiased
//    bilinear resize + pooled means + 4->32->4 MLP + argmax)
// ---------------------------------------------------------------------------
__global__ __launch_bounds__(1024) void dir_kernel(
    const float* __restrict__ xg,
    const float* __restrict__ w1, const float* __restrict__ b1,
    const float* __restrict__ w2, const float* __restrict__ b2,
    int* __restrict__ isvert)
{
    __shared__ float s[1024];
    __shared__ float sred[4 * 32];
    __shared__ float s4[4];
    int b = blockIdx.x, t = threadIdx.x;
    s[t] = xg[b * 1024 + t];
    __syncthreads();

    int i = t >> 5, j = t & 31;
    const float inv = 1.0f / 1.0625f;  // kernel_scale = max(34/32,1)

    // gh: raw 34x32 (H-dim padded grad along W), antialiased resize H 34->32
    float sf = (i + 0.5f) * 1.0625f - 0.5f;
    int x0 = (int)floorf(sf) - 1;
    int jm = refl(j - 1), jp = refl(j + 1);
    float gh = 0.f, ws = 0.f;
#pragma unroll
    for (int dx = 0; dx < 4; ++dx) {
        int xx = x0 + dx;
        if (xx < 0 || xx > 33) continue;
        float w = 1.0f - fabsf(sf - (float)xx) * inv;
        if (w <= 0.f) continue;
        int rr = refl(xx - 1);
        gh += w * fabsf(s[rr * 32 + jp] - s[rr * 32 + jm]);
        ws += w;
    }
    gh /= ws;

    // gv: raw 32x34 (grad along H), antialiased resize W 34->32
    float sfj = (j + 0.5f) * 1.0625f - 0.5f;
    int y0 = (int)floorf(sfj) - 1;
    int im = refl(i - 1), ip = refl(i + 1);
    float gv = 0.f; ws = 0.f;
#pragma unroll
    for (int dx = 0; dx < 4; ++dx) {
        int xx = y0 + dx;
        if (xx < 0 || xx > 33) continue;
        float w = 1.0f - fabsf(sfj - (float)xx) * inv;
        if (w <= 0.f) continue;
        int cc = refl(xx - 1);
        gv += w * fabsf(s[ip * 32 + cc] - s[im * 32 + cc]);
        ws += w;
    }
    gv /= ws;

    float gd = 0.5f * (gh + gv);
    float ga = fabsf(gh - gv);
    // pool_mean == weighted mean with 3x3 border-count weights / (9*1024)
    float cw = ((i == 0 || i == 31) ? 2.f : 3.f) * ((j == 0 || j == 31) ? 2.f : 3.f);
    float v0 = gh * cw, v1 = gv * cw, v2 = gd * cw, v3 = ga * cw;
#pragma unroll
    for (int o = 16; o; o >>= 1) {
        v0 += __shfl_xor_sync(0xffffffffu, v0, o);
        v1 += __shfl_xor_sync(0xffffffffu, v1, o);
        v2 += __shfl_xor_sync(0xffffffffu, v2, o);
        v3 += __shfl_xor_sync(0xffffffffu, v3, o);
    }
    int wi = t >> 5, ln = t & 31;
    if (ln == 0) {
        sred[0 * 32 + wi] = v0; sred[1 * 32 + wi] = v1;
        sred[2 * 32 + wi] = v2; sred[3 * 32 + wi] = v3;
    }
    __syncthreads();
    if (t < 4) {
        float a = 0.f;
        for (int w = 0; w < 32; w++) a += sred[t * 32 + w];
        s4[t] = a * (1.0f / (9.0f * 1024.0f));
    }
    __syncthreads();
    if (t == 0) {
        float sc0 = s4[0], sc1 = s4[1], sc2 = s4[2], sc3 = s4[3];
        float lg[4] = {b2[0], b2[1], b2[2], b2[3]};
        for (int jj = 0; jj < 32; jj++) {
            float h = b1[jj] + sc0 * w1[0 * 32 + jj] + sc1 * w1[1 * 32 + jj]
                             + sc2 * w1[2 * 32 + jj] + sc3 * w1[3 * 32 + jj];
            h = fmaxf(h, 0.f);
            lg[0] += h * w2[jj * 4 + 0];
            lg[1] += h * w2[jj * 4 + 1];
            lg[2] += h * w2[jj * 4 + 2];
            lg[3] += h * w2[jj * 4 + 3];
        }
        int bi = 0; float bv = lg[0];
        for (int m = 1; m < 4; m++) if (lg[m] > bv) { bv = lg[m]; bi = m; }
        isvert[b] = (bi == 1) ? 1 : 0;
    }
}

// ---------------------------------------------------------------------------
// 3) Gather (apply optional HW transpose per batch)
// ---------------------------------------------------------------------------
__global__ __launch_bounds__(256) void gather_kernel(
    const float* __restrict__ xn, const int* __restrict__ isv,
    float* __restrict__ seq)
{
    int idx = blockIdx.x * 256 + threadIdx.x;         // NTOK*96 float4s
    int c4 = idx % 96;
    int r  = idx / 96;
    int b = r >> 10, t = r & 1023;
    int src = isv[b] ? (((t & 31) << 5) | (t >> 5)) : t;
    ((float4*)seq)[(size_t)r * 96 + c4] =
        ((const float4*)xn)[(size_t)((b << 10) | src) * 96 + c4];
}

// ---------------------------------------------------------------------------
// 4) Generic 128x128 SIMT GEMM (fp32), MODE: 0 plain, 1 bias+softplus,
//    2 residual-add
// ---------------------------------------------------------------------------
template <int MODE>
__global__ __launch_bounds__(256) void gemm128(
    const float* __restrict__ A, const float* __restrict__ B,
    float* __restrict__ C, int M, int N, int K,
    const float* __restrict__ bias, const float* __restrict__ res)
{
    __shared__ float As[16][132];
    __shared__ float Bs[16][128];
    int tid = threadIdx.x;
    int tx = tid & 15, ty = tid >> 4;

    const float* Ab = A + (size_t)blockIdx.y * 128 * K;
    const float* Bb = B + blockIdx.x * 128;

    float acc[8][8];
#pragma unroll
    for (int i = 0; i < 8; i++)
#pragma unroll
        for (int j = 0; j < 8; j++) acc[i][j] = 0.f;

    int arow = tid >> 2;
    int akk  = (tid & 3) << 2;
    int bn   = (tid & 31) << 2;
    int bk0  = tid >> 5;

    for (int k0 = 0; k0 < K; k0 += 16) {
        float4 a0 = *(const float4*)(Ab + (size_t)arow * K + k0 + akk);
        float4 a1 = *(const float4*)(Ab + (size_t)(arow + 64) * K + k0 + akk);
        float4 b0 = *(const float4*)(Bb + (size_t)(k0 + bk0) * N + bn);
        float4 b1 = *(const float4*)(Bb + (size_t)(k0 + bk0 + 8) * N + bn);
        __syncthreads();
        As[akk + 0][arow] = a0.x; As[akk + 1][arow] = a0.y;
        As[akk + 2][arow] = a0.z; As[akk + 3][arow] = a0.w;
        As[akk + 0][arow + 64] = a1.x; As[akk + 1][arow + 64] = a1.y;
        As[akk + 2][arow + 64] = a1.z; As[akk + 3][arow + 64] = a1.w;
        *(float4*)&Bs[bk0][bn]     = b0;
        *(float4*)&Bs[bk0 + 8][bn] = b1;
        __syncthreads();
#pragma unroll
        for (int kk = 0; kk < 16; kk++) {
            float av[8], bv[8];
            *(float4*)&av[0] = *(const float4*)&As[kk][ty * 8];
            *(float4*)&av[4] = *(const float4*)&As[kk][ty * 8 + 4];
            *(float4*)&bv[0] = *(const float4*)&Bs[kk][tx * 8];
            *(float4*)&bv[4] = *(const float4*)&Bs[kk][tx * 8 + 4];
#pragma unroll
            for (int i = 0; i < 8; i++)
#pragma unroll
                for (int j = 0; j < 8; j++)
                    acc[i][j] = fmaf(av[i], bv[j], acc[i][j]);
        }
    }

    int row0 = blockIdx.y * 128 + ty * 8;
    int col0 = blockIdx.x * 128 + tx * 8;
#pragma unroll
    for (int i = 0; i < 8; i++) {
        int r = row0 + i;
#pragma unroll
        for (int j = 0; j < 8; j += 4) {
            float4 v = make_float4(acc[i][j], acc[i][j + 1], acc[i][j + 2], acc[i][j + 3]);
            if (MODE == 1) {
                v.x = softplusf(v.x + bias[col0 + j + 0]);
                v.y = softplusf(v.y + bias[col0 + j + 1]);
                v.z = softplusf(v.z + bias[col0 + j + 2]);
                v.w = softplusf(v.w + bias[col0 + j + 3]);
            } else if (MODE == 2) {
                float4 rr = *(const float4*)(res + (size_t)r * N + col0 + j);
                v.x += rr.x; v.y += rr.y; v.z += rr.z; v.w += rr.w;
            }
            *(float4*)(C + (size_t)r * N + col0 + j) = v;
        }
    }
}

// ---------------------------------------------------------------------------
// 5) Depthwise conv (k=3, zero pad) + SiLU on xz[:, :768] -> xc
// ---------------------------------------------------------------------------
__global__ __launch_bounds__(256) void conv_silu_kernel(
    const float* __restrict__ xz, const float* __restrict__ w,
    const float* __restrict__ cb, float* __restrict__ xc)
{
    int idx = blockIdx.x * 256 + threadIdx.x;  // NTOK * 192
    int d4 = idx % 192;
    int bt = idx / 192;
    int t  = bt & 1023;
    int d  = d4 * 4;
    const float* base = xz + (size_t)bt * XZW + d;
    float4 c  = *(const float4*)base;
    float4 p  = (t > 0)    ? *(const float4*)(base - XZW) : make_float4(0, 0, 0, 0);
    float4 nx = (t < 1023) ? *(const float4*)(base + XZW) : make_float4(0, 0, 0, 0);
    float4 o;
    o.x = p.x * w[(d + 0) * 3 + 0] + c.x * w[(d + 0) * 3 + 1] + nx.x * w[(d + 0) * 3 + 2] + cb[d + 0];
    o.y = p.y * w[(d + 1) * 3 + 0] + c.y * w[(d + 1) * 3 + 1] + nx.y * w[(d + 1) * 3 + 2] + cb[d + 1];
    o.z = p.z * w[(d + 2) * 3 + 0] + c.z * w[(d + 2) * 3 + 1] + nx.z * w[(d + 2) * 3 + 2] + cb[d + 2];
    o.w = p.w * w[(d + 3) * 3 + 0] + c.w * w[(d + 3) * 3 + 1] + nx.w * w[(d + 3) * 3 + 2] + cb[d + 3];
    o.x = siluf(o.x); o.y = siluf(o.y); o.z = siluf(o.z); o.w = siluf(o.w);
    *(float4*)(xc + (size_t)bt * DI + d) = o;
}

// ---------------------------------------------------------------------------
// 6) x_proj: BC = xc @ x_proj_w  (8192 x 32, K=768). Thread = (row, 4 cols).
// ---------------------------------------------------------------------------
__global__ __launch_bounds__(256) void xproj_kernel(
    const float* __restrict__ xc, const float* __restrict__ w,
    float* __restrict__ bcout)
{
    int idx = blockIdx.x * 256 + threadIdx.x;  // 8192*8
    int q   = idx & 7;
    int row = idx >> 3;
    const float* a = xc + (size_t)row * DI;
    float4 acc = make_float4(0, 0, 0, 0);
#pragma unroll 2
    for (int k = 0; k < DI; k += 4) {
        float4 av = *(const float4*)(a + k);
        float4 w0 = *(const float4*)(w + (size_t)(k + 0) * 32 + q * 4);
        float4 w1 = *(const float4*)(w + (size_t)(k + 1) * 32 + q * 4);
        float4 w2 = *(const float4*)(w + (size_t)(k + 2) * 32 + q * 4);
        float4 w3 = *(const float4*)(w + (size_t)(k + 3) * 32 + q * 4);
        acc.x += av.x * w0.x + av.y * w1.x + av.z * w2.x + av.w * w3.x;
        acc.y += av.x * w0.y + av.y * w1.y + av.z * w2.y + av.w * w3.y;
        acc.z += av.x * w0.z + av.y * w1.z + av.z * w2.z + av.w * w3.z;
        acc.w += av.x * w0.w + av.y * w1.w + av.z * w2.w + av.w * w3.w;
    }
    *(float4*)(bcout + (size_t)row * 32 + q * 4) = acc;
}

// ---------------------------------------------------------------------------
// 7) Selective scan. 4 threads per (b,d), each owns 4 states. Shuffle-reduce
//    y over the 4-lane group; epilogue applies +D*xc and *silu(z).
// ---------------------------------------------------------------------------
__global__ __launch_bounds__(128) void scan_kernel(
    const float* __restrict__ delta, const float* __restrict__ xc,
    const float* __restrict__ bc, const float* __restrict__ xz,
    const float* __restrict__ A_log, const float* __restrict__ Dv,
    float* __restrict__ y)
{
    int b   = blockIdx.y;
    int tid = threadIdx.x;
    int dloc = tid >> 2;
    int nq   = tid & 3;
    int d = blockIdx.x * 32 + dloc;

    const float L2E = 1.44269504f;
    float4 al = *(const float4*)(A_log + (size_t)d * DS + nq * 4);
    float a0 = -__expf(al.x) * L2E;
    float a1 = -__expf(al.y) * L2E;
    float a2 = -__expf(al.z) * L2E;
    float a3 = -__expf(al.w) * L2E;
    float Dd = Dv[d];

    float h0 = 0.f, h1 = 0.f, h2 = 0.f, h3 = 0.f;
    const float* dp  = delta + (size_t)(b * 1024) * DI + d;
    const float* xp  = xc    + (size_t)(b * 1024) * DI + d;
    const float* bcp = bc    + (size_t)(b * 1024) * 32 + nq * 4;
    const float* zp  = xz    + (size_t)(b * 1024) * XZW + DI + d;
    float* yp = y + (size_t)(b * 1024) * DI + d;

    // register prefetch pipeline
    float de = dp[0];
    float xv = xp[0];
    float4 Bv = *(const float4*)(bcp);
    float4 Cv = *(const float4*)(bcp + 16);

#pragma unroll 2
    for (int t = 0; t < 1024; ++t) {
        int tn = (t + 1 < 1024) ? t + 1 : 1023;
        float de_n = dp[(size_t)tn * DI];
        float xv_n = xp[(size_t)tn * DI];
        float4 Bv_n = *(const float4*)(bcp + (size_t)tn * 32);
        float4 Cv_n = *(const float4*)(bcp + (size_t)tn * 32 + 16);

        float dx = de * xv;
        float e0 = ex2_approx(de * a0);
        float e1 = ex2_approx(de * a1);
        float e2 = ex2_approx(de * a2);
        float e3 = ex2_approx(de * a3);
        h0 = fmaf(e0, h0, dx * Bv.x);
        h1 = fmaf(e1, h1, dx * Bv.y);
        h2 = fmaf(e2, h2, dx * Bv.z);
        h3 = fmaf(e3, h3, dx * Bv.w);
        float acc = h0 * Cv.x + h1 * Cv.y + h2 * Cv.z + h3 * Cv.w;
        acc += __shfl_xor_sync(0xffffffffu, acc, 1);
        acc += __shfl_xor_sync(0xffffffffu, acc, 2);
        if (nq == 0) {
            float z = zp[(size_t)t * XZW];
            yp[(size_t)t * DI] = (acc + Dd * xv) * siluf(z);
        }
        de = de_n; xv = xv_n; Bv = Bv_n; Cv = Cv_n;
    }
}

// ---------------------------------------------------------------------------
// launch
// ---------------------------------------------------------------------------
extern "C" void kernel_launch(void* const* d_in, const int* in_sizes, int n_in,
                              void* d_out, int out_size)
{
    const float* x          = (const float*)d_in[0];
    const float* ln_g       = (const float*)d_in[1];
    const float* ln_b       = (const float*)d_in[2];
    const float* mlp_w1     = (const float*)d_in[3];
    const float* mlp_b1     = (const float*)d_in[4];
    const float* mlp_w2     = (const float*)d_in[5];
    const float* mlp_b2     = (const float*)d_in[6];
    const float* in_proj_w  = (const float*)d_in[7];
    const float* conv_w     = (const float*)d_in[8];
    const float* conv_b     = (const float*)d_in[9];
    const float* x_proj_w   = (const float*)d_in[10];
    const float* dt_w       = (const float*)d_in[11];
    const float* dt_b       = (const float*)d_in[12];
    const float* A_log      = (const float*)d_in[13];
    const float* Dv         = (const float*)d_in[14];
    const float* out_proj_w = (const float*)d_in[15];
    float* out = (float*)d_out;

    float *xn, *seq, *xg, *xz, *xc, *delta, *bc, *yv;
    int* isv;
    cudaGetSymbolAddress((void**)&xn,    g_xn);
    cudaGetSymbolAddress((void**)&seq,   g_seq);
    cudaGetSymbolAddress((void**)&xg,    g_xg);
    cudaGetSymbolAddress((void**)&isv,   g_isv);
    cudaGetSymbolAddress((void**)&xz,    g_xz);
    cudaGetSymbolAddress((void**)&xc,    g_xc);
    cudaGetSymbolAddress((void**)&delta, g_delta);
    cudaGetSymbolAddress((void**)&bc,    g_bc);
    cudaGetSymbolAddress((void**)&yv,    g_y);

    // 1. LayerNorm (+ channel-mean image)
    ln_kernel<<<NTOK / 8, 256>>>(x, ln_g, ln_b, xn, xg);
    // 2. direction selection
    dir_kernel<<<BATCH, 1024>>>(xg, mlp_w1, mlp_b1, mlp_w2, mlp_b2, isv);
    // 3. gather (optional transpose)
    gather_kernel<<<(NTOK * 96) / 256, 256>>>(xn, isv, seq);
    // 4. in_proj: xz = seq @ in_proj_w   (8192 x 1536, K=384)
    gemm128<0><<<dim3(XZW / 128, NTOK / 128), 256>>>(
        seq, in_proj_w, xz, NTOK, XZW, DIM, nullptr, nullptr);
    // 5. depthwise conv + silu
    conv_silu_kernel<<<(NTOK * (DI / 4)) / 256, 256>>>(xz, conv_w, conv_b, xc);
    // 6. x_proj: bc = xc @ x_proj_w      (8192 x 32, K=768)
    xproj_kernel<<<(NTOK * 8) / 256, 256>>>(xc, x_proj_w, bc);
    // 7. dt: delta = softplus(xc @ dt_w + dt_b)   (8192 x 768, K=768)
    gemm128<1><<<dim3(DI / 128, NTOK / 128), 256>>>(
        xc, dt_w, delta, NTOK, DI, DI, dt_b, nullptr);
    // 8. selective scan (+gate)
    scan_kernel<<<dim3(DI / 32, BATCH), 128>>>(delta, xc, bc, xz, A_log, Dv, yv);
    // 9. out_proj + residual: out = x + yv @ out_proj_w  (8192 x 384, K=768)
    gemm128<2><<<dim3(DIM / 128, NTOK / 128), 256>>>(
        yv, out_proj_w, out, NTOK, DIM, DI, nullptr, x);
}

// round 2
// speedup vs baseline: 1.6228x; 1.6228x over previous
#include <cuda_runtime.h>
#include <cuda_bf16.h>
#include <math.h>

// ---------------------------------------------------------------------------
// Problem constants
// ---------------------------------------------------------------------------
#define BATCH   8
#define HW      32
#define L_SEQ   1024          // 32*32
#define DIM     384
#define DI      768           // D_INNER
#define DS      16            // D_STATE
#define XZW     1536          // 2*D_INNER
#define NTOK    (BATCH*L_SEQ) // 8192

// chunked scan params
#define NC      32            // number of chunks
#define TC      32            // steps per chunk
#define CH_STRIDE (BATCH*DI*DS)  // 98304 per-chunk state slice

// ---------------------------------------------------------------------------
// Scratch (device globals -- no allocation allowed in kernel_launch)
// ---------------------------------------------------------------------------
__device__ float g_xn   [NTOK*DIM];   // layernorm output
__device__ float g_seq  [NTOK*DIM];   // gathered (maybe transposed) sequence
__device__ float g_xg   [NTOK];       // per-pixel channel mean of xn
__device__ int   g_isv  [BATCH];      // is_vert flag per batch
__device__ float g_xz   [NTOK*XZW];   // in_proj output
__device__ float g_xc   [NTOK*DI];    // conv+silu output
__device__ float g_delta[NTOK*DI];    // softplus(dt) output
__device__ float g_bc   [NTOK*2*DS];  // x_proj output (B then C)
__device__ float g_y    [NTOK*DI];    // scan output (gated)
__device__ float g_P    [NC*CH_STRIDE]; // chunk transfer: multiplier
__device__ float g_Q    [NC*CH_STRIDE]; // chunk transfer: offset
__device__ float g_h0   [NC*CH_STRIDE]; // chunk start states

// ---------------------------------------------------------------------------
// Helpers
// ---------------------------------------------------------------------------
__device__ __forceinline__ float ex2_approx(float x) {
    float r;
    asm("ex2.approx.f32 %0, %1;" : "=f"(r) : "f"(x));
    return r;
}
__device__ __forceinline__ float softplusf(float x) {
    return fmaxf(x, 0.f) + log1pf(__expf(-fabsf(x)));
}
__device__ __forceinline__ float siluf(float x) {
    return x / (1.f + __expf(-x));
}
__device__ __forceinline__ int refl(int v) {
    return v < 0 ? -v : (v > 31 ? 62 - v : v);
}

// ---------------------------------------------------------------------------
// 1) LayerNorm: warp per token, also emits channel-mean image g_xg
// ---------------------------------------------------------------------------
__global__ __launch_bounds__(256) void ln_kernel(
    const float* __restrict__ x, const float* __restrict__ gam,
    const float* __restrict__ bet, float* __restrict__ xn,
    float* __restrict__ xgm)
{
    int warp = threadIdx.x >> 5, lane = threadIdx.x & 31;
    int r = blockIdx.x * 8 + warp;
    const float4* xp = (const float4*)(x + (size_t)r * DIM);
    float4 v[3];
    float s = 0.f, s2 = 0.f;
#pragma unroll
    for (int i = 0; i < 3; i++) {
        v[i] = xp[lane + 32 * i];
        s  += v[i].x + v[i].y + v[i].z + v[i].w;
        s2 += v[i].x * v[i].x + v[i].y * v[i].y + v[i].z * v[i].z + v[i].w * v[i].w;
    }
#pragma unroll
    for (int o = 16; o; o >>= 1) {
        s  += __shfl_xor_sync(0xffffffffu, s,  o);
        s2 += __shfl_xor_sync(0xffffffffu, s2, o);
    }
    float mu   = s * (1.f / DIM);
    float var  = s2 * (1.f / DIM) - mu * mu;
    float rstd = rsqrtf(var + 1e-5f);

    float xs = 0.f;
    float4* op = (float4*)(xn + (size_t)r * DIM);
    const float4* gp = (const float4*)gam;
    const float4* bp = (const float4*)bet;
#pragma unroll
    for (int i = 0; i < 3; i++) {
        float4 g4 = gp[lane + 32 * i];
        float4 b4 = bp[lane + 32 * i];
        float4 o4;
        o4.x = (v[i].x - mu) * rstd * g4.x + b4.x;
        o4.y = (v[i].y - mu) * rstd * g4.y + b4.y;
        o4.z = (v[i].z - mu) * rstd * g4.z + b4.z;
        o4.w = (v[i].w - mu) * rstd * g4.w + b4.w;
        xs += o4.x + o4.y + o4.z + o4.w;
        op[lane + 32 * i] = o4;
    }
#pragma unroll
    for (int o = 16; o; o >>= 1) xs += __shfl_xor_sync(0xffffffffu, xs, o);
    if (lane == 0) xgm[r] = xs * (1.f / DIM);
}

// ---------------------------------------------------------------------------
// 2) Direction selection: one block per batch
// ---------------------------------------------------------------------------
__global__ __launch_bounds__(1024) void dir_kernel(
    const float* __restrict__ xg,
    const float* __restrict__ w1, const float* __restrict__ b1,
    const float* __restrict__ w2, const float* __restrict__ b2,
    int* __restrict__ isvert)
{
    __shared__ float s[1024];
    __shared__ float sred[4 * 32];
    __shared__ float s4[4];
    int b = blockIdx.x, t = threadIdx.x;
    s[t] = xg[b * 1024 + t];
    __syncthreads();

    int i = t >> 5, j = t & 31;
    const float inv = 1.0f / 1.0625f;

    float sf = (i + 0.5f) * 1.0625f - 0.5f;
    int x0 = (int)floorf(sf) - 1;
    int jm = refl(j - 1), jp = refl(j + 1);
    float gh = 0.f, ws = 0.f;
#pragma unroll
    for (int dx = 0; dx < 4; ++dx) {
        int xx = x0 + dx;
        if (xx < 0 || xx > 33) continue;
        float w = 1.0f - fabsf(sf - (float)xx) * inv;
        if (w <= 0.f) continue;
        int rr = refl(xx - 1);
        gh += w * fabsf(s[rr * 32 + jp] - s[rr * 32 + jm]);
        ws += w;
    }
    gh /= ws;

    float sfj = (j + 0.5f) * 1.0625f - 0.5f;
    int y0 = (int)floorf(sfj) - 1;
    int im = refl(i - 1), ip = refl(i + 1);
    float gv = 0.f; ws = 0.f;
#pragma unroll
    for (int dx = 0; dx < 4; ++dx) {
        int xx = y0 + dx;
        if (xx < 0 || xx > 33) continue;
        float w = 1.0f - fabsf(sfj - (float)xx) * inv;
        if (w <= 0.f) continue;
        int cc = refl(xx - 1);
        gv += w * fabsf(s[ip * 32 + cc] - s[im * 32 + cc]);
        ws += w;
    }
    gv /= ws;

    float gd = 0.5f * (gh + gv);
    float ga = fabsf(gh - gv);
    float cw = ((i == 0 || i == 31) ? 2.f : 3.f) * ((j == 0 || j == 31) ? 2.f : 3.f);
    float v0 = gh * cw, v1 = gv * cw, v2 = gd * cw, v3 = ga * cw;
#pragma unroll
    for (int o = 16; o; o >>= 1) {
        v0 += __shfl_xor_sync(0xffffffffu, v0, o);
        v1 += __shfl_xor_sync(0xffffffffu, v1, o);
        v2 += __shfl_xor_sync(0xffffffffu, v2, o);
        v3 += __shfl_xor_sync(0xffffffffu, v3, o);
    }
    int wi = t >> 5, ln = t & 31;
    if (ln == 0) {
        sred[0 * 32 + wi] = v0; sred[1 * 32 + wi] = v1;
        sred[2 * 32 + wi] = v2; sred[3 * 32 + wi] = v3;
    }
    __syncthreads();
    if (t < 4) {
        float a = 0.f;
        for (int w = 0; w < 32; w++) a += sred[t * 32 + w];
        s4[t] = a * (1.0f / (9.0f * 1024.0f));
    }
    __syncthreads();
    if (t == 0) {
        float sc0 = s4[0], sc1 = s4[1], sc2 = s4[2], sc3 = s4[3];
        float lg[4] = {b2[0], b2[1], b2[2], b2[3]};
        for (int jj = 0; jj < 32; jj++) {
            float h = b1[jj] + sc0 * w1[0 * 32 + jj] + sc1 * w1[1 * 32 + jj]
                             + sc2 * w1[2 * 32 + jj] + sc3 * w1[3 * 32 + jj];
            h = fmaxf(h, 0.f);
            lg[0] += h * w2[jj * 4 + 0];
            lg[1] += h * w2[jj * 4 + 1];
            lg[2] += h * w2[jj * 4 + 2];
            lg[3] += h * w2[jj * 4 + 3];
        }
        int bi = 0; float bv = lg[0];
        for (int m = 1; m < 4; m++) if (lg[m] > bv) { bv = lg[m]; bi = m; }
        isvert[b] = (bi == 1) ? 1 : 0;
    }
}

// ---------------------------------------------------------------------------
// 3) Gather (apply optional HW transpose per batch)
// ---------------------------------------------------------------------------
__global__ __launch_bounds__(256) void gather_kernel(
    const float* __restrict__ xn, const int* __restrict__ isv,
    float* __restrict__ seq)
{
    int idx = blockIdx.x * 256 + threadIdx.x;
    int c4 = idx % 96;
    int r  = idx / 96;
    int b = r >> 10, t = r & 1023;
    int src = isv[b] ? (((t & 31) << 5) | (t >> 5)) : t;
    ((float4*)seq)[(size_t)r * 96 + c4] =
        ((const float4*)xn)[(size_t)((b << 10) | src) * 96 + c4];
}

// ---------------------------------------------------------------------------
// 4) Generic 128x128 SIMT GEMM (fp32), MODE: 0 plain, 1 bias+softplus,
//    2 residual-add
// ---------------------------------------------------------------------------
template <int MODE>
__global__ __launch_bounds__(256) void gemm128(
    const float* __restrict__ A, const float* __restrict__ B,
    float* __restrict__ C, int M, int N, int K,
    const float* __restrict__ bias, const float* __restrict__ res)
{
    __shared__ float As[16][132];
    __shared__ float Bs[16][128];
    int tid = threadIdx.x;
    int tx = tid & 15, ty = tid >> 4;

    const float* Ab = A + (size_t)blockIdx.y * 128 * K;
    const float* Bb = B + blockIdx.x * 128;

    float acc[8][8];
#pragma unroll
    for (int i = 0; i < 8; i++)
#pragma unroll
        for (int j = 0; j < 8; j++) acc[i][j] = 0.f;

    int arow = tid >> 2;
    int akk  = (tid & 3) << 2;
    int bn   = (tid & 31) << 2;
    int bk0  = tid >> 5;

    for (int k0 = 0; k0 < K; k0 += 16) {
        float4 a0 = *(const float4*)(Ab + (size_t)arow * K + k0 + akk);
        float4 a1 = *(const float4*)(Ab + (size_t)(arow + 64) * K + k0 + akk);
        float4 b0 = *(const float4*)(Bb + (size_t)(k0 + bk0) * N + bn);
        float4 b1 = *(const float4*)(Bb + (size_t)(k0 + bk0 + 8) * N + bn);
        __syncthreads();
        As[akk + 0][arow] = a0.x; As[akk + 1][arow] = a0.y;
        As[akk + 2][arow] = a0.z; As[akk + 3][arow] = a0.w;
        As[akk + 0][arow + 64] = a1.x; As[akk + 1][arow + 64] = a1.y;
        As[akk + 2][arow + 64] = a1.z; As[akk + 3][arow + 64] = a1.w;
        *(float4*)&Bs[bk0][bn]     = b0;
        *(float4*)&Bs[bk0 + 8][bn] = b1;
        __syncthreads();
#pragma unroll
        for (int kk = 0; kk < 16; kk++) {
            float av[8], bv[8];
            *(float4*)&av[0] = *(const float4*)&As[kk][ty * 8];
            *(float4*)&av[4] = *(const float4*)&As[kk][ty * 8 + 4];
            *(float4*)&bv[0] = *(const float4*)&Bs[kk][tx * 8];
            *(float4*)&bv[4] = *(const float4*)&Bs[kk][tx * 8 + 4];
#pragma unroll
            for (int i = 0; i < 8; i++)
#pragma unroll
                for (int j = 0; j < 8; j++)
                    acc[i][j] = fmaf(av[i], bv[j], acc[i][j]);
        }
    }

    int row0 = blockIdx.y * 128 + ty * 8;
    int col0 = blockIdx.x * 128 + tx * 8;
#pragma unroll
    for (int i = 0; i < 8; i++) {
        int r = row0 + i;
#pragma unroll
        for (int j = 0; j < 8; j += 4) {
            float4 v = make_float4(acc[i][j], acc[i][j + 1], acc[i][j + 2], acc[i][j + 3]);
            if (MODE == 1) {
                v.x = softplusf(v.x + bias[col0 + j + 0]);
                v.y = softplusf(v.y + bias[col0 + j + 1]);
                v.z = softplusf(v.z + bias[col0 + j + 2]);
                v.w = softplusf(v.w + bias[col0 + j + 3]);
            } else if (MODE == 2) {
                float4 rr = *(const float4*)(res + (size_t)r * N + col0 + j);
                v.x += rr.x; v.y += rr.y; v.z += rr.z; v.w += rr.w;
            }
            *(float4*)(C + (size_t)r * N + col0 + j) = v;
        }
    }
}

// ---------------------------------------------------------------------------
// 5) Depthwise conv (k=3, zero pad) + SiLU on xz[:, :768] -> xc
// ---------------------------------------------------------------------------
__global__ __launch_bounds__(256) void conv_silu_kernel(
    const float* __restrict__ xz, const float* __restrict__ w,
    const float* __restrict__ cb, float* __restrict__ xc)
{
    int idx = blockIdx.x * 256 + threadIdx.x;
    int d4 = idx % 192;
    int bt = idx / 192;
    int t  = bt & 1023;
    int d  = d4 * 4;
    const float* base = xz + (size_t)bt * XZW + d;
    float4 c  = *(const float4*)base;
    float4 p  = (t > 0)    ? *(const float4*)(base - XZW) : make_float4(0, 0, 0, 0);
    float4 nx = (t < 1023) ? *(const float4*)(base + XZW) : make_float4(0, 0, 0, 0);
    float4 o;
    o.x = p.x * w[(d + 0) * 3 + 0] + c.x * w[(d + 0) * 3 + 1] + nx.x * w[(d + 0) * 3 + 2] + cb[d + 0];
    o.y = p.y * w[(d + 1) * 3 + 0] + c.y * w[(d + 1) * 3 + 1] + nx.y * w[(d + 1) * 3 + 2] + cb[d + 1];
    o.z = p.z * w[(d + 2) * 3 + 0] + c.z * w[(d + 2) * 3 + 1] + nx.z * w[(d + 2) * 3 + 2] + cb[d + 2];
    o.w = p.w * w[(d + 3) * 3 + 0] + c.w * w[(d + 3) * 3 + 1] + nx.w * w[(d + 3) * 3 + 2] + cb[d + 3];
    o.x = siluf(o.x); o.y = siluf(o.y); o.z = siluf(o.z); o.w = siluf(o.w);
    *(float4*)(xc + (size_t)bt * DI + d) = o;
}

// ---------------------------------------------------------------------------
// 6) x_proj (smem staged): warp per row; lane computes one of 32 outputs.
// ---------------------------------------------------------------------------
__global__ __launch_bounds__(256) void xproj_kernel(
    const float* __restrict__ xc, const float* __restrict__ w,
    float* __restrict__ bcout)
{
    __shared__ float srow[8][DI];
    int warp = threadIdx.x >> 5, lane = threadIdx.x & 31;
    int row = blockIdx.x * 8 + warp;
    const float4* a = (const float4*)(xc + (size_t)row * DI);
    float4* sp = (float4*)srow[warp];
#pragma unroll
    for (int i = 0; i < 6; i++) sp[lane + 32 * i] = a[lane + 32 * i];
    __syncwarp();
    float acc = 0.f;
#pragma unroll 4
    for (int k = 0; k < DI; k += 4) {
        float4 av = *(const float4*)&srow[warp][k];
        acc = fmaf(av.x, w[(k + 0) * 32 + lane], acc);
        acc = fmaf(av.y, w[(k + 1) * 32 + lane], acc);
        acc = fmaf(av.z, w[(k + 2) * 32 + lane], acc);
        acc = fmaf(av.w, w[(k + 3) * 32 + lane], acc);
    }
    bcout[(size_t)row * 32 + lane] = acc;
}

// ---------------------------------------------------------------------------
// 7a) Chunked scan pass 1: per-chunk transfer (P, Q) per (b,d,n-quad,chunk)
// ---------------------------------------------------------------------------
__global__ __launch_bounds__(128) void scan_chunk1(
    const float* __restrict__ delta, const float* __restrict__ xc,
    const float* __restrict__ bc, const float* __restrict__ A_log,
    float* __restrict__ Pout, float* __restrict__ Qout)
{
    int b = blockIdx.y, c = blockIdx.z;
    int tid = threadIdx.x;
    int dloc = tid >> 2, nq = tid & 3;
    int d = blockIdx.x * 32 + dloc;

    const float L2E = 1.44269504f;
    float4 al = *(const float4*)(A_log + (size_t)d * DS + nq * 4);
    float a0 = -__expf(al.x) * L2E;
    float a1 = -__expf(al.y) * L2E;
    float a2 = -__expf(al.z) * L2E;
    float a3 = -__expf(al.w) * L2E;

    int t0 = c * TC;
    const float* dp  = delta + (size_t)(b * 1024 + t0) * DI + d;
    const float* xp  = xc    + (size_t)(b * 1024 + t0) * DI + d;
    const float* bcp = bc    + (size_t)(b * 1024 + t0) * 32 + nq * 4;

    float q0 = 0.f, q1 = 0.f, q2 = 0.f, q3 = 0.f, S = 0.f;
#pragma unroll 4
    for (int t = 0; t < TC; ++t) {
        float de = dp[(size_t)t * DI];
        float xv = xp[(size_t)t * DI];
        float4 Bv = *(const float4*)(bcp + (size_t)t * 32);
        float dx = de * xv;
        float e0 = ex2_approx(de * a0);
        float e1 = ex2_approx(de * a1);
        float e2 = ex2_approx(de * a2);
        float e3 = ex2_approx(de * a3);
        q0 = fmaf(e0, q0, dx * Bv.x);
        q1 = fmaf(e1, q1, dx * Bv.y);
        q2 = fmaf(e2, q2, dx * Bv.z);
        q3 = fmaf(e3, q3, dx * Bv.w);
        S += de;
    }
    size_t idx = (size_t)c * CH_STRIDE + ((size_t)(b * DI + d)) * DS + nq * 4;
    *(float4*)(Pout + idx) = make_float4(ex2_approx(a0 * S), ex2_approx(a1 * S),
                                         ex2_approx(a2 * S), ex2_approx(a3 * S));
    *(float4*)(Qout + idx) = make_float4(q0, q1, q2, q3);
}

// ---------------------------------------------------------------------------
// 7b) Chunked scan pass 2: sequential combine over chunks (coalesced)
// ---------------------------------------------------------------------------
__global__ __launch_bounds__(256) void scan_chunk2(
    const float* __restrict__ P, const float* __restrict__ Q,
    float* __restrict__ H0)
{
    int idx = blockIdx.x * 256 + threadIdx.x;   // 0 .. CH_STRIDE-1
    float h = 0.f;
#pragma unroll
    for (int c = 0; c < NC; ++c) {
        size_t o = (size_t)c * CH_STRIDE + idx;
        H0[o] = h;
        h = fmaf(P[o], h, Q[o]);
    }
}

// ---------------------------------------------------------------------------
// 7c) Chunked scan pass 3: re-scan chunk from true start state, emit gated y
// ---------------------------------------------------------------------------
__global__ __launch_bounds__(128) void scan_chunk3(
    const float* __restrict__ delta, const float* __restrict__ xc,
    const float* __restrict__ bc, const float* __restrict__ xz,
    const float* __restrict__ A_log, const float* __restrict__ Dv,
    const float* __restrict__ H0, float* __restrict__ y)
{
    int b = blockIdx.y, c = blockIdx.z;
    int tid = threadIdx.x;
    int dloc = tid >> 2, nq = tid & 3;
    int d = blockIdx.x * 32 + dloc;

    const float L2E = 1.44269504f;
    float4 al = *(const float4*)(A_log + (size_t)d * DS + nq * 4);
    float a0 = -__expf(al.x) * L2E;
    float a1 = -__expf(al.y) * L2E;
    float a2 = -__expf(al.z) * L2E;
    float a3 = -__expf(al.w) * L2E;
    float Dd = Dv[d];

    size_t sidx = (size_t)c * CH_STRIDE + ((size_t)(b * DI + d)) * DS + nq * 4;
    float4 h4 = *(const float4*)(H0 + sidx);
    float h0 = h4.x, h1 = h4.y, h2 = h4.z, h3 = h4.w;

    int t0 = c * TC;
    const float* dp  = delta + (size_t)(b * 1024 + t0) * DI + d;
    const float* xp  = xc    + (size_t)(b * 1024 + t0) * DI + d;
    const float* bcp = bc    + (size_t)(b * 1024 + t0) * 32 + nq * 4;
    const float* zp  = xz    + (size_t)(b * 1024 + t0) * XZW + DI + d;
    float* yp        = y     + (size_t)(b * 1024 + t0) * DI + d;

#pragma unroll 4
    for (int t = 0; t < TC; ++t) {
        float de = dp[(size_t)t * DI];
        float xv = xp[(size_t)t * DI];
        float4 Bv = *(const float4*)(bcp + (size_t)t * 32);
        float4 Cv = *(const float4*)(bcp + (size_t)t * 32 + 16);
        float dx = de * xv;
        float e0 = ex2_approx(de * a0);
        float e1 = ex2_approx(de * a1);
        float e2 = ex2_approx(de * a2);
        float e3 = ex2_approx(de * a3);
        h0 = fmaf(e0, h0, dx * Bv.x);
        h1 = fmaf(e1, h1, dx * Bv.y);
        h2 = fmaf(e2, h2, dx * Bv.z);
        h3 = fmaf(e3, h3, dx * Bv.w);
        float acc = h0 * Cv.x + h1 * Cv.y + h2 * Cv.z + h3 * Cv.w;
        acc += __shfl_xor_sync(0xffffffffu, acc, 1);
        acc += __shfl_xor_sync(0xffffffffu, acc, 2);
        if (nq == 0) {
            float z = zp[(size_t)t * XZW];
            yp[(size_t)t * DI] = (acc + Dd * xv) * siluf(z);
        }
    }
}

// ---------------------------------------------------------------------------
// launch
// ---------------------------------------------------------------------------
extern "C" void kernel_launch(void* const* d_in, const int* in_sizes, int n_in,
                              void* d_out, int out_size)
{
    const float* x          = (const float*)d_in[0];
    const float* ln_g       = (const float*)d_in[1];
    const float* ln_b       = (const float*)d_in[2];
    const float* mlp_w1     = (const float*)d_in[3];
    const float* mlp_b1     = (const float*)d_in[4];
    const float* mlp_w2     = (const float*)d_in[5];
    const float* mlp_b2     = (const float*)d_in[6];
    const float* in_proj_w  = (const float*)d_in[7];
    const float* conv_w     = (const float*)d_in[8];
    const float* conv_b     = (const float*)d_in[9];
    const float* x_proj_w   = (const float*)d_in[10];
    const float* dt_w       = (const float*)d_in[11];
    const float* dt_b       = (const float*)d_in[12];
    const float* A_log      = (const float*)d_in[13];
    const float* Dv         = (const float*)d_in[14];
    const float* out_proj_w = (const float*)d_in[15];
    float* out = (float*)d_out;

    float *xn, *seq, *xg, *xz, *xc, *delta, *bc, *yv, *Pp, *Qp, *H0p;
    int* isv;
    cudaGetSymbolAddress((void**)&xn,    g_xn);
    cudaGetSymbolAddress((void**)&seq,   g_seq);
    cudaGetSymbolAddress((void**)&xg,    g_xg);
    cudaGetSymbolAddress((void**)&isv,   g_isv);
    cudaGetSymbolAddress((void**)&xz,    g_xz);
    cudaGetSymbolAddress((void**)&xc,    g_xc);
    cudaGetSymbolAddress((void**)&delta, g_delta);
    cudaGetSymbolAddress((void**)&bc,    g_bc);
    cudaGetSymbolAddress((void**)&yv,    g_y);
    cudaGetSymbolAddress((void**)&Pp,    g_P);
    cudaGetSymbolAddress((void**)&Qp,    g_Q);
    cudaGetSymbolAddress((void**)&H0p,   g_h0);

    // 1. LayerNorm (+ channel-mean image)
    ln_kernel<<<NTOK / 8, 256>>>(x, ln_g, ln_b, xn, xg);
    // 2. direction selection
    dir_kernel<<<BATCH, 1024>>>(xg, mlp_w1, mlp_b1, mlp_w2, mlp_b2, isv);
    // 3. gather (optional transpose)
    gather_kernel<<<(NTOK * 96) / 256, 256>>>(xn, isv, seq);
    // 4. in_proj: xz = seq @ in_proj_w   (8192 x 1536, K=384)
    gemm128<0><<<dim3(XZW / 128, NTOK / 128), 256>>>(
        seq, in_proj_w, xz, NTOK, XZW, DIM, nullptr, nullptr);
    // 5. depthwise conv + silu
    conv_silu_kernel<<<(NTOK * (DI / 4)) / 256, 256>>>(xz, conv_w, conv_b, xc);
    // 6. x_proj: bc = xc @ x_proj_w      (8192 x 32, K=768)
    xproj_kernel<<<NTOK / 8, 256>>>(xc, x_proj_w, bc);
    // 7. dt: delta = softplus(xc @ dt_w + dt_b)   (8192 x 768, K=768)
    gemm128<1><<<dim3(DI / 128, NTOK / 128), 256>>>(
        xc, dt_w, delta, NTOK, DI, DI, dt_b, nullptr);
    // 8. chunked selective scan (3 passes)
    scan_chunk1<<<dim3(DI / 32, BATCH, NC), 128>>>(delta, xc, bc, A_log, Pp, Qp);
    scan_chunk2<<<CH_STRIDE / 256, 256>>>(Pp, Qp, H0p);
    scan_chunk3<<<dim3(DI / 32, BATCH, NC), 128>>>(delta, xc, bc, xz, A_log, Dv,
                                                   H0p, yv);
    // 9. out_proj + residual: out = x + yv @ out_proj_w  (8192 x 384, K=768)
    gemm128<2><<<dim3(DIM / 128, NTOK / 128), 256>>>(
        yv, out_proj_w, out, NTOK, DIM, DI, nullptr, x);
}

// round 3
// speedup vs baseline: 3.6112x; 2.2253x over previous
#include <cuda_runtime.h>
#include <cuda_bf16.h>
#include <math.h>
#include <stdint.h>

// ---------------------------------------------------------------------------
// Problem constants
// ---------------------------------------------------------------------------
#define BATCH   8
#define HW      32
#define L_SEQ   1024
#define DIM     384
#define DI      768
#define DS      16
#define XZW     1536
#define NTOK    (BATCH*L_SEQ)

#define NC      32
#define TC      32
#define CH_STRIDE (BATCH*DI*DS)

// ---------------------------------------------------------------------------
// Scratch
// ---------------------------------------------------------------------------
__device__ float g_xn   [NTOK*DIM];
__device__ float g_xg   [NTOK];
__device__ int   g_isv  [BATCH];
__device__ float g_xz   [NTOK*XZW];
__device__ float g_xc   [NTOK*DI];
__device__ float g_delta[NTOK*DI];
__device__ float g_bc   [NTOK*2*DS];
__device__ float g_P    [NC*CH_STRIDE];
__device__ float g_Q    [NC*CH_STRIDE];
__device__ float g_h0   [NC*CH_STRIDE];

// bf16 operands
__device__ __nv_bfloat16 g_seqb[NTOK*DIM];     // gathered sequence (bf16)
__device__ __nv_bfloat16 g_xcb [NTOK*DI];      // conv+silu output (bf16)
__device__ __nv_bfloat16 g_yb  [NTOK*DI];      // scan output (bf16)
__device__ __nv_bfloat16 g_wA  [XZW*DIM];      // in_proj_w^T  [N=1536][K=384]
__device__ __nv_bfloat16 g_wD  [DI*DI];        // dt_w^T       [N=768][K=768]
__device__ __nv_bfloat16 g_wO  [DIM*DI];       // out_proj_w^T [N=384][K=768]

// ---------------------------------------------------------------------------
// Helpers
// ---------------------------------------------------------------------------
__device__ __forceinline__ float ex2_approx(float x) {
    float r;
    asm("ex2.approx.f32 %0, %1;" : "=f"(r) : "f"(x));
    return r;
}
__device__ __forceinline__ float softplusf(float x) {
    return fmaxf(x, 0.f) + log1pf(__expf(-fabsf(x)));
}
__device__ __forceinline__ float siluf(float x) {
    return x / (1.f + __expf(-x));
}
__device__ __forceinline__ int refl(int v) {
    return v < 0 ? -v : (v > 31 ? 62 - v : v);
}
__device__ __forceinline__ void mma16816(float* d, const uint32_t* a,
                                          const uint32_t* b) {
    asm volatile(
        "mma.sync.aligned.m16n8k16.row.col.f32.bf16.bf16.f32 "
        "{%0,%1,%2,%3}, {%4,%5,%6,%7}, {%8,%9}, {%0,%1,%2,%3};"
        : "+f"(d[0]), "+f"(d[1]), "+f"(d[2]), "+f"(d[3])
        : "r"(a[0]), "r"(a[1]), "r"(a[2]), "r"(a[3]), "r"(b[0]), "r"(b[1]));
}

// ---------------------------------------------------------------------------
// 0) Weight transpose + bf16 convert: wt[n][k] = bf16(w[k][n])
// ---------------------------------------------------------------------------
__global__ __launch_bounds__(256) void convert_wT(
    const float* __restrict__ w, __nv_bfloat16* __restrict__ wt, int K, int N)
{
    __shared__ float tile[32][33];
    int nb = blockIdx.x * 32, kb = blockIdx.y * 32;
    int tx = threadIdx.x, ty = threadIdx.y;
#pragma unroll
    for (int i = 0; i < 4; i++)
        tile[ty + i * 8][tx] = w[(size_t)(kb + ty + i * 8) * N + nb + tx];
    __syncthreads();
#pragma unroll
    for (int i = 0; i < 4; i++)
        wt[(size_t)(nb + ty + i * 8) * K + kb + tx] =
            __float2bfloat16(tile[tx][ty + i * 8]);
}

// ---------------------------------------------------------------------------
// 1) LayerNorm: warp per token, also emits channel-mean image g_xg
// ---------------------------------------------------------------------------
__global__ __launch_bounds__(256) void ln_kernel(
    const float* __restrict__ x, const float* __restrict__ gam,
    const float* __restrict__ bet, float* __restrict__ xn,
    float* __restrict__ xgm)
{
    int warp = threadIdx.x >> 5, lane = threadIdx.x & 31;
    int r = blockIdx.x * 8 + warp;
    const float4* xp = (const float4*)(x + (size_t)r * DIM);
    float4 v[3];
    float s = 0.f, s2 = 0.f;
#pragma unroll
    for (int i = 0; i < 3; i++) {
        v[i] = xp[lane + 32 * i];
        s  += v[i].x + v[i].y + v[i].z + v[i].w;
        s2 += v[i].x * v[i].x + v[i].y * v[i].y + v[i].z * v[i].z + v[i].w * v[i].w;
    }
#pragma unroll
    for (int o = 16; o; o >>= 1) {
        s  += __shfl_xor_sync(0xffffffffu, s,  o);
        s2 += __shfl_xor_sync(0xffffffffu, s2, o);
    }
    float mu   = s * (1.f / DIM);
    float var  = s2 * (1.f / DIM) - mu * mu;
    float rstd = rsqrtf(var + 1e-5f);

    float xs = 0.f;
    float4* op = (float4*)(xn + (size_t)r * DIM);
    const float4* gp = (const float4*)gam;
    const float4* bp = (const float4*)bet;
#pragma unroll
    for (int i = 0; i < 3; i++) {
        float4 g4 = gp[lane + 32 * i];
        float4 b4 = bp[lane + 32 * i];
        float4 o4;
        o4.x = (v[i].x - mu) * rstd * g4.x + b4.x;
        o4.y = (v[i].y - mu) * rstd * g4.y + b4.y;
        o4.z = (v[i].z - mu) * rstd * g4.z + b4.z;
        o4.w = (v[i].w - mu) * rstd * g4.w + b4.w;
        xs += o4.x + o4.y + o4.z + o4.w;
        op[lane + 32 * i] = o4;
    }
#pragma unroll
    for (int o = 16; o; o >>= 1) xs += __shfl_xor_sync(0xffffffffu, xs, o);
    if (lane == 0) xgm[r] = xs * (1.f / DIM);
}

// ---------------------------------------------------------------------------
// 2) Direction selection
// ---------------------------------------------------------------------------
__global__ __launch_bounds__(1024) void dir_kernel(
    const float* __restrict__ xg,
    const float* __restrict__ w1, const float* __restrict__ b1,
    const float* __restrict__ w2, const float* __restrict__ b2,
    int* __restrict__ isvert)
{
    __shared__ float s[1024];
    __shared__ float sred[4 * 32];
    __shared__ float s4[4];
    int b = blockIdx.x, t = threadIdx.x;
    s[t] = xg[b * 1024 + t];
    __syncthreads();

    int i = t >> 5, j = t & 31;
    const float inv = 1.0f / 1.0625f;

    float sf = (i + 0.5f) * 1.0625f - 0.5f;
    int x0 = (int)floorf(sf) - 1;
    int jm = refl(j - 1), jp = refl(j + 1);
    float gh = 0.f, ws = 0.f;
#pragma unroll
    for (int dx = 0; dx < 4; ++dx) {
        int xx = x0 + dx;
        if (xx < 0 || xx > 33) continue;
        float w = 1.0f - fabsf(sf - (float)xx) * inv;
        if (w <= 0.f) continue;
        int rr = refl(xx - 1);
        gh += w * fabsf(s[rr * 32 + jp] - s[rr * 32 + jm]);
        ws += w;
    }
    gh /= ws;

    float sfj = (j + 0.5f) * 1.0625f - 0.5f;
    int y0 = (int)floorf(sfj) - 1;
    int im = refl(i - 1), ip = refl(i + 1);
    float gv = 0.f; ws = 0.f;
#pragma unroll
    for (int dx = 0; dx < 4; ++dx) {
        int xx = y0 + dx;
        if (xx < 0 || xx > 33) continue;
        float w = 1.0f - fabsf(sfj - (float)xx) * inv;
        if (w <= 0.f) continue;
        int cc = refl(xx - 1);
        gv += w * fabsf(s[ip * 32 + cc] - s[im * 32 + cc]);
        ws += w;
    }
    gv /= ws;

    float gd = 0.5f * (gh + gv);
    float ga = fabsf(gh - gv);
    float cw = ((i == 0 || i == 31) ? 2.f : 3.f) * ((j == 0 || j == 31) ? 2.f : 3.f);
    float v0 = gh * cw, v1 = gv * cw, v2 = gd * cw, v3 = ga * cw;
#pragma unroll
    for (int o = 16; o; o >>= 1) {
        v0 += __shfl_xor_sync(0xffffffffu, v0, o);
        v1 += __shfl_xor_sync(0xffffffffu, v1, o);
        v2 += __shfl_xor_sync(0xffffffffu, v2, o);
        v3 += __shfl_xor_sync(0xffffffffu, v3, o);
    }
    int wi = t >> 5, ln = t & 31;
    if (ln == 0) {
        sred[0 * 32 + wi] = v0; sred[1 * 32 + wi] = v1;
        sred[2 * 32 + wi] = v2; sred[3 * 32 + wi] = v3;
    }
    __syncthreads();
    if (t < 4) {
        float a = 0.f;
        for (int w = 0; w < 32; w++) a += sred[t * 32 + w];
        s4[t] = a * (1.0f / (9.0f * 1024.0f));
    }
    __syncthreads();
    if (t == 0) {
        float sc0 = s4[0], sc1 = s4[1], sc2 = s4[2], sc3 = s4[3];
        float lg[4] = {b2[0], b2[1], b2[2], b2[3]};
        for (int jj = 0; jj < 32; jj++) {
            float h = b1[jj] + sc0 * w1[0 * 32 + jj] + sc1 * w1[1 * 32 + jj]
                             + sc2 * w1[2 * 32 + jj] + sc3 * w1[3 * 32 + jj];
            h = fmaxf(h, 0.f);
            lg[0] += h * w2[jj * 4 + 0];
            lg[1] += h * w2[jj * 4 + 1];
            lg[2] += h * w2[jj * 4 + 2];
            lg[3] += h * w2[jj * 4 + 3];
        }
        int bi = 0; float bv = lg[0];
        for (int m = 1; m < 4; m++) if (lg[m] > bv) { bv = lg[m]; bi = m; }
        isvert[b] = (bi == 1) ? 1 : 0;
    }
}

// ---------------------------------------------------------------------------
// 3) Gather (optional transpose) -> bf16 sequence
// ---------------------------------------------------------------------------
__global__ __launch_bounds__(256) void gather_kernel(
    const float* __restrict__ xn, const int* __restrict__ isv,
    __nv_bfloat16* __restrict__ seqb)
{
    int idx = blockIdx.x * 256 + threadIdx.x;
    int c4 = idx % 96;
    int r  = idx / 96;
    int b = r >> 10, t = r & 1023;
    int src = isv[b] ? (((t & 31) << 5) | (t >> 5)) : t;
    float4 v = ((const float4*)xn)[(size_t)((b << 10) | src) * 96 + c4];
    __nv_bfloat162 lo = __floats2bfloat162_rn(v.x, v.y);
    __nv_bfloat162 hi = __floats2bfloat162_rn(v.z, v.w);
    uint2 o;
    o.x = *(uint32_t*)&lo;
    o.y = *(uint32_t*)&hi;
    ((uint2*)seqb)[(size_t)r * 96 + c4] = o;
}

// ---------------------------------------------------------------------------
// 4) bf16 tensor-core GEMM: C[M,N] = A[M,K] @ Bt[N,K]^T (fp32 accum)
//    MODE: 0 plain, 1 bias+softplus, 2 residual-add
// ---------------------------------------------------------------------------
template <int MODE>
__global__ __launch_bounds__(256) void gemm_bf16(
    const __nv_bfloat16* __restrict__ A,
    const __nv_bfloat16* __restrict__ Bt,
    float* __restrict__ C, int M, int N, int K,
    const float* __restrict__ bias, const float* __restrict__ res)
{
    constexpr int BK  = 32;
    constexpr int LDS = 40;   // padded smem stride (elems): conflict-free, 16B-aligned
    __shared__ __nv_bfloat16 As[2][128 * LDS];
    __shared__ __nv_bfloat16 Bs[2][128 * LDS];

    int tid  = threadIdx.x;
    int warp = tid >> 5, lane = tid & 31;
    int wm = (warp >> 1) * 32;   // 4 warps along M
    int wn = (warp & 1) * 64;    // 2 warps along N

    const __nv_bfloat16* Ag = A  + (size_t)(blockIdx.y * 128) * K;
    const __nv_bfloat16* Bg = Bt + (size_t)(blockIdx.x * 128) * K;

    int lrow = tid >> 2;         // 0..63
    int lkq  = (tid & 3) * 8;    // 0,8,16,24

    float acc[2][8][4];
#pragma unroll
    for (int i = 0; i < 2; i++)
#pragma unroll
        for (int j = 0; j < 8; j++)
#pragma unroll
            for (int q = 0; q < 4; q++) acc[i][j][q] = 0.f;

    uint4 pa0, pa1, pb0, pb1;
    // prologue fetch k0 = 0
    pa0 = *(const uint4*)(Ag + (size_t)lrow * K + lkq);
    pa1 = *(const uint4*)(Ag + (size_t)(lrow + 64) * K + lkq);
    pb0 = *(const uint4*)(Bg + (size_t)lrow * K + lkq);
    pb1 = *(const uint4*)(Bg + (size_t)(lrow + 64) * K + lkq);
    *(uint4*)&As[0][lrow * LDS + lkq]        = pa0;
    *(uint4*)&As[0][(lrow + 64) * LDS + lkq] = pa1;
    *(uint4*)&Bs[0][lrow * LDS + lkq]        = pb0;
    *(uint4*)&Bs[0][(lrow + 64) * LDS + lkq] = pb1;
    __syncthreads();

    int buf = 0;
    for (int k0 = BK; k0 <= K; k0 += BK) {
        if (k0 < K) {
            pa0 = *(const uint4*)(Ag + (size_t)lrow * K + k0 + lkq);
            pa1 = *(const uint4*)(Ag + (size_t)(lrow + 64) * K + k0 + lkq);
            pb0 = *(const uint4*)(Bg + (size_t)lrow * K + k0 + lkq);
            pb1 = *(const uint4*)(Bg + (size_t)(lrow + 64) * K + k0 + lkq);
        }
        // compute current buffer (two k16 steps)
#pragma unroll
        for (int s = 0; s < 2; s++) {
            int ko = s * 16;
            uint32_t af[2][4], bfr[8][2];
#pragma unroll
            for (int i = 0; i < 2; i++) {
                int r0 = wm + i * 16 + (lane >> 2);
                int c  = ko + (lane & 3) * 2;
                af[i][0] = *(const uint32_t*)&As[buf][r0 * LDS + c];
                af[i][1] = *(const uint32_t*)&As[buf][(r0 + 8) * LDS + c];
                af[i][2] = *(const uint32_t*)&As[buf][r0 * LDS + c + 8];
                af[i][3] = *(const uint32_t*)&As[buf][(r0 + 8) * LDS + c + 8];
            }
#pragma unroll
            for (int j = 0; j < 8; j++) {
                int n0 = wn + j * 8 + (lane >> 2);
                int c  = ko + (lane & 3) * 2;
                bfr[j][0] = *(const uint32_t*)&Bs[buf][n0 * LDS + c];
                bfr[j][1] = *(const uint32_t*)&Bs[buf][n0 * LDS + c + 8];
            }
#pragma unroll
            for (int i = 0; i < 2; i++)
#pragma unroll
                for (int j = 0; j < 8; j++)
                    mma16816(acc[i][j], af[i], bfr[j]);
        }
        if (k0 < K) {
            int nb = buf ^ 1;
            *(uint4*)&As[nb][lrow * LDS + lkq]        = pa0;
            *(uint4*)&As[nb][(lrow + 64) * LDS + lkq] = pa1;
            *(uint4*)&Bs[nb][lrow * LDS + lkq]        = pb0;
            *(uint4*)&Bs[nb][(lrow + 64) * LDS + lkq] = pb1;
            __syncthreads();
            buf = nb;
        }
    }

    // epilogue
#pragma unroll
    for (int i = 0; i < 2; i++) {
        int row0 = blockIdx.y * 128 + wm + i * 16 + (lane >> 2);
#pragma unroll
        for (int j = 0; j < 8; j++) {
            int col = blockIdx.x * 128 + wn + j * 8 + (lane & 3) * 2;
#pragma unroll
            for (int h = 0; h < 2; h++) {
                int r = row0 + h * 8;
                float2 v = make_float2(acc[i][j][h * 2], acc[i][j][h * 2 + 1]);
                if (MODE == 1) {
                    v.x = softplusf(v.x + bias[col]);
                    v.y = softplusf(v.y + bias[col + 1]);
                } else if (MODE == 2) {
                    float2 rr = *(const float2*)(res + (size_t)r * N + col);
                    v.x += rr.x; v.y += rr.y;
                }
                *(float2*)(C + (size_t)r * N + col) = v;
            }
        }
    }
}

// ---------------------------------------------------------------------------
// 5) Depthwise conv (k=3) + SiLU -> xc (fp32) and xcb (bf16)
// ---------------------------------------------------------------------------
__global__ __launch_bounds__(256) void conv_silu_kernel(
    const float* __restrict__ xz, const float* __restrict__ w,
    const float* __restrict__ cb, float* __restrict__ xc,
    __nv_bfloat16* __restrict__ xcb)
{
    int idx = blockIdx.x * 256 + threadIdx.x;
    int d4 = idx % 192;
    int bt = idx / 192;
    int t  = bt & 1023;
    int d  = d4 * 4;
    const float* base = xz + (size_t)bt * XZW + d;
    float4 c  = *(const float4*)base;
    float4 p  = (t > 0)    ? *(const float4*)(base - XZW) : make_float4(0, 0, 0, 0);
    float4 nx = (t < 1023) ? *(const float4*)(base + XZW) : make_float4(0, 0, 0, 0);
    float4 o;
    o.x = p.x * w[(d + 0) * 3 + 0] + c.x * w[(d + 0) * 3 + 1] + nx.x * w[(d + 0) * 3 + 2] + cb[d + 0];
    o.y = p.y * w[(d + 1) * 3 + 0] + c.y * w[(d + 1) * 3 + 1] + nx.y * w[(d + 1) * 3 + 2] + cb[d + 1];
    o.z = p.z * w[(d + 2) * 3 + 0] + c.z * w[(d + 2) * 3 + 1] + nx.z * w[(d + 2) * 3 + 2] + cb[d + 2];
    o.w = p.w * w[(d + 3) * 3 + 0] + c.w * w[(d + 3) * 3 + 1] + nx.w * w[(d + 3) * 3 + 2] + cb[d + 3];
    o.x = siluf(o.x); o.y = siluf(o.y); o.z = siluf(o.z); o.w = siluf(o.w);
    *(float4*)(xc + (size_t)bt * DI + d) = o;
    __nv_bfloat162 p0 = __floats2bfloat162_rn(o.x, o.y);
    __nv_bfloat162 p1 = __floats2bfloat162_rn(o.z, o.w);
    uint2 ob; ob.x = *(uint32_t*)&p0; ob.y = *(uint32_t*)&p1;
    *(uint2*)(xcb + (size_t)bt * DI + d) = ob;
}

// ---------------------------------------------------------------------------
// 6) x_proj (smem staged): warp per row; lane computes one of 32 outputs.
// ---------------------------------------------------------------------------
__global__ __launch_bounds__(256) void xproj_kernel(
    const float* __restrict__ xc, const float* __restrict__ w,
    float* __restrict__ bcout)
{
    __shared__ float srow[8][DI];
    int warp = threadIdx.x >> 5, lane = threadIdx.x & 31;
    int row = blockIdx.x * 8 + warp;
    const float4* a = (const float4*)(xc + (size_t)row * DI);
    float4* sp = (float4*)srow[warp];
#pragma unroll
    for (int i = 0; i < 6; i++) sp[lane + 32 * i] = a[lane + 32 * i];
    __syncwarp();
    float acc = 0.f;
#pragma unroll 4
    for (int k = 0; k < DI; k += 4) {
        float4 av = *(const float4*)&srow[warp][k];
        acc = fmaf(av.x, w[(k + 0) * 32 + lane], acc);
        acc = fmaf(av.y, w[(k + 1) * 32 + lane], acc);
        acc = fmaf(av.z, w[(k + 2) * 32 + lane], acc);
        acc = fmaf(av.w, w[(k + 3) * 32 + lane], acc);
    }
    bcout[(size_t)row * 32 + lane] = acc;
}

// ---------------------------------------------------------------------------
// 7a) Chunked scan pass 1
// ---------------------------------------------------------------------------
__global__ __launch_bounds__(128) void scan_chunk1(
    const float* __restrict__ delta, const float* __restrict__ xc,
    const float* __restrict__ bc, const float* __restrict__ A_log,
    float* __restrict__ Pout, float* __restrict__ Qout)
{
    int b = blockIdx.y, c = blockIdx.z;
    int tid = threadIdx.x;
    int dloc = tid >> 2, nq = tid & 3;
    int d = blockIdx.x * 32 + dloc;

    const float L2E = 1.44269504f;
    float4 al = *(const float4*)(A_log + (size_t)d * DS + nq * 4);
    float a0 = -__expf(al.x) * L2E;
    float a1 = -__expf(al.y) * L2E;
    float a2 = -__expf(al.z) * L2E;
    float a3 = -__expf(al.w) * L2E;

    int t0 = c * TC;
    const float* dp  = delta + (size_t)(b * 1024 + t0) * DI + d;
    const float* xp  = xc    + (size_t)(b * 1024 + t0) * DI + d;
    const float* bcp = bc    + (size_t)(b * 1024 + t0) * 32 + nq * 4;

    float q0 = 0.f, q1 = 0.f, q2 = 0.f, q3 = 0.f, S = 0.f;
#pragma unroll 4
    for (int t = 0; t < TC; ++t) {
        float de = dp[(size_t)t * DI];
        float xv = xp[(size_t)t * DI];
        float4 Bv = *(const float4*)(bcp + (size_t)t * 32);
        float dx = de * xv;
        float e0 = ex2_approx(de * a0);
        float e1 = ex2_approx(de * a1);
        float e2 = ex2_approx(de * a2);
        float e3 = ex2_approx(de * a3);
        q0 = fmaf(e0, q0, dx * Bv.x);
        q1 = fmaf(e1, q1, dx * Bv.y);
        q2 = fmaf(e2, q2, dx * Bv.z);
        q3 = fmaf(e3, q3, dx * Bv.w);
        S += de;
    }
    size_t idx = (size_t)c * CH_STRIDE + ((size_t)(b * DI + d)) * DS + nq * 4;
    *(float4*)(Pout + idx) = make_float4(ex2_approx(a0 * S), ex2_approx(a1 * S),
                                         ex2_approx(a2 * S), ex2_approx(a3 * S));
    *(float4*)(Qout + idx) = make_float4(q0, q1, q2, q3);
}

// ---------------------------------------------------------------------------
// 7b) Chunked scan pass 2
// ---------------------------------------------------------------------------
__global__ __launch_bounds__(256) void scan_chunk2(
    const float* __restrict__ P, const float* __restrict__ Q,
    float* __restrict__ H0)
{
    int idx = blockIdx.x * 256 + threadIdx.x;
    float h = 0.f;
#pragma unroll
    for (int c = 0; c < NC; ++c) {
        size_t o = (size_t)c * CH_STRIDE + idx;
        H0[o] = h;
        h = fmaf(P[o], h, Q[o]);
    }
}

// ---------------------------------------------------------------------------
// 7c) Chunked scan pass 3: emit gated y (bf16)
// ---------------------------------------------------------------------------
__global__ __launch_bounds__(128) void scan_chunk3(
    const float* __restrict__ delta, const float* __restrict__ xc,
    const float* __restrict__ bc, const float* __restrict__ xz,
    const float* __restrict__ A_log, const float* __restrict__ Dv,
    const float* __restrict__ H0, __nv_bfloat16* __restrict__ yb)
{
    int b = blockIdx.y, c = blockIdx.z;
    int tid = threadIdx.x;
    int dloc = tid >> 2, nq = tid & 3;
    int d = blockIdx.x * 32 + dloc;

    const float L2E = 1.44269504f;
    float4 al = *(const float4*)(A_log + (size_t)d * DS + nq * 4);
    float a0 = -__expf(al.x) * L2E;
    float a1 = -__expf(al.y) * L2E;
    float a2 = -__expf(al.z) * L2E;
    float a3 = -__expf(al.w) * L2E;
    float Dd = Dv[d];

    size_t sidx = (size_t)c * CH_STRIDE + ((size_t)(b * DI + d)) * DS + nq * 4;
    float4 h4 = *(const float4*)(H0 + sidx);
    float h0 = h4.x, h1 = h4.y, h2 = h4.z, h3 = h4.w;

    int t0 = c * TC;
    const float* dp  = delta + (size_t)(b * 1024 + t0) * DI + d;
    const float* xp  = xc    + (size_t)(b * 1024 + t0) * DI + d;
    const float* bcp = bc    + (size_t)(b * 1024 + t0) * 32 + nq * 4;
    const float* zp  = xz    + (size_t)(b * 1024 + t0) * XZW + DI + d;
    __nv_bfloat16* yp = yb   + (size_t)(b * 1024 + t0) * DI + d;

#pragma unroll 4
    for (int t = 0; t < TC; ++t) {
        float de = dp[(size_t)t * DI];
        float xv = xp[(size_t)t * DI];
        float4 Bv = *(const float4*)(bcp + (size_t)t * 32);
        float4 Cv = *(const float4*)(bcp + (size_t)t * 32 + 16);
        float dx = de * xv;
        float e0 = ex2_approx(de * a0);
        float e1 = ex2_approx(de * a1);
        float e2 = ex2_approx(de * a2);
        float e3 = ex2_approx(de * a3);
        h0 = fmaf(e0, h0, dx * Bv.x);
        h1 = fmaf(e1, h1, dx * Bv.y);
        h2 = fmaf(e2, h2, dx * Bv.z);
        h3 = fmaf(e3, h3, dx * Bv.w);
        float acc = h0 * Cv.x + h1 * Cv.y + h2 * Cv.z + h3 * Cv.w;
        acc += __shfl_xor_sync(0xffffffffu, acc, 1);
        acc += __shfl_xor_sync(0xffffffffu, acc, 2);
        if (nq == 0) {
            float z = zp[(size_t)t * XZW];
            yp[(size_t)t * DI] = __float2bfloat16((acc + Dd * xv) * siluf(z));
        }
    }
}

// ---------------------------------------------------------------------------
// launch
// ---------------------------------------------------------------------------
extern "C" void kernel_launch(void* const* d_in, const int* in_sizes, int n_in,
                              void* d_out, int out_size)
{
    const float* x          = (const float*)d_in[0];
    const float* ln_g       = (const float*)d_in[1];
    const float* ln_b       = (const float*)d_in[2];
    const float* mlp_w1     = (const float*)d_in[3];
    const float* mlp_b1     = (const float*)d_in[4];
    const float* mlp_w2     = (const float*)d_in[5];
    const float* mlp_b2     = (const float*)d_in[6];
    const float* in_proj_w  = (const float*)d_in[7];
    const float* conv_w     = (const float*)d_in[8];
    const float* conv_b     = (const float*)d_in[9];
    const float* x_proj_w   = (const float*)d_in[10];
    const float* dt_w       = (const float*)d_in[11];
    const float* dt_b       = (const float*)d_in[12];
    const float* A_log      = (const float*)d_in[13];
    const float* Dv         = (const float*)d_in[14];
    const float* out_proj_w = (const float*)d_in[15];
    float* out = (float*)d_out;

    float *xn, *xg, *xz, *xc, *delta, *bc, *Pp, *Qp, *H0p;
    __nv_bfloat16 *seqb, *xcb, *yb, *wA, *wD, *wO;
    int* isv;
    cudaGetSymbolAddress((void**)&xn,    g_xn);
    cudaGetSymbolAddress((void**)&xg,    g_xg);
    cudaGetSymbolAddress((void**)&isv,   g_isv);
    cudaGetSymbolAddress((void**)&xz,    g_xz);
    cudaGetSymbolAddress((void**)&xc,    g_xc);
    cudaGetSymbolAddress((void**)&delta, g_delta);
    cudaGetSymbolAddress((void**)&bc,    g_bc);
    cudaGetSymbolAddress((void**)&Pp,    g_P);
    cudaGetSymbolAddress((void**)&Qp,    g_Q);
    cudaGetSymbolAddress((void**)&H0p,   g_h0);
    cudaGetSymbolAddress((void**)&seqb,  g_seqb);
    cudaGetSymbolAddress((void**)&xcb,   g_xcb);
    cudaGetSymbolAddress((void**)&yb,    g_yb);
    cudaGetSymbolAddress((void**)&wA,    g_wA);
    cudaGetSymbolAddress((void**)&wD,    g_wD);
    cudaGetSymbolAddress((void**)&wO,    g_wO);

    // weight transpose + bf16 convert
    convert_wT<<<dim3(XZW / 32, DIM / 32), dim3(32, 8)>>>(in_proj_w, wA, DIM, XZW);
    convert_wT<<<dim3(DI / 32, DI / 32),   dim3(32, 8)>>>(dt_w, wD, DI, DI);
    convert_wT<<<dim3(DIM / 32, DI / 32),  dim3(32, 8)>>>(out_proj_w, wO, DI, DIM);

    // 1. LayerNorm (+ channel-mean image)
    ln_kernel<<<NTOK / 8, 256>>>(x, ln_g, ln_b, xn, xg);
    // 2. direction selection
    dir_kernel<<<BATCH, 1024>>>(xg, mlp_w1, mlp_b1, mlp_w2, mlp_b2, isv);
    // 3. gather (optional transpose) -> bf16
    gather_kernel<<<(NTOK * 96) / 256, 256>>>(xn, isv, seqb);
    // 4. in_proj: xz = seq @ in_proj_w   (8192 x 1536, K=384)
    gemm_bf16<0><<<dim3(XZW / 128, NTOK / 128), 256>>>(
        seqb, wA, xz, NTOK, XZW, DIM, nullptr, nullptr);
    // 5. depthwise conv + silu (fp32 + bf16 outputs)
    conv_silu_kernel<<<(NTOK * (DI / 4)) / 256, 256>>>(xz, conv_w, conv_b, xc, xcb);
    // 6. x_proj
    xproj_kernel<<<NTOK / 8, 256>>>(xc, x_proj_w, bc);
    // 7. dt: delta = softplus(xc @ dt_w + dt_b)
    gemm_bf16<1><<<dim3(DI / 128, NTOK / 128), 256>>>(
        xcb, wD, delta, NTOK, DI, DI, dt_b, nullptr);
    // 8. chunked selective scan
    scan_chunk1<<<dim3(DI / 32, BATCH, NC), 128>>>(delta, xc, bc, A_log, Pp, Qp);
    scan_chunk2<<<CH_STRIDE / 256, 256>>>(Pp, Qp, H0p);
    scan_chunk3<<<dim3(DI / 32, BATCH, NC), 128>>>(delta, xc, bc, xz, A_log, Dv,
                                                   H0p, yb);
    // 9. out_proj + residual
    gemm_bf16<2><<<dim3(DIM / 128, NTOK / 128), 256>>>(
        yb, wO, out, NTOK, DIM, DI, nullptr, x);
}

// round 5
// speedup vs baseline: 3.7649x; 1.0426x over previous
#include <cuda_runtime.h>
#include <cuda_bf16.h>
#include <math.h>
#include <stdint.h>

// ---------------------------------------------------------------------------
// Problem constants
// ---------------------------------------------------------------------------
#define BATCH   8
#define HW      32
#define L_SEQ   1024
#define DIM     384
#define DI      768
#define DS      16
#define XZW     1536
#define NTOK    (BATCH*L_SEQ)

#define NC      32
#define TC      32
#define CH_STRIDE (BATCH*DI*DS)

// ---------------------------------------------------------------------------
// Scratch
// ---------------------------------------------------------------------------
__device__ float g_xn   [NTOK*DIM];
__device__ float g_xg   [NTOK];
__device__ int   g_isv  [BATCH];
__device__ float g_xz   [NTOK*XZW];
__device__ float g_xc   [NTOK*DI];
__device__ float g_delta[NTOK*DI];
__device__ float g_bc   [NTOK*2*DS];
__device__ float g_P    [NC*CH_STRIDE];
__device__ float g_Q    [NC*CH_STRIDE];
__device__ float g_h0   [NC*CH_STRIDE];

__device__ __nv_bfloat16 g_seqb[NTOK*DIM];
__device__ __nv_bfloat16 g_xcb [NTOK*DI];
__device__ __nv_bfloat16 g_yb  [NTOK*DI];
__device__ __nv_bfloat16 g_wA  [XZW*DIM];   // in_proj_w^T  [N=1536][K=384]
__device__ __nv_bfloat16 g_wD  [DI*DI];     // dt_w^T       [N=768][K=768]
__device__ __nv_bfloat16 g_wO  [DIM*DI];    // out_proj_w^T [N=384][K=768]

// ---------------------------------------------------------------------------
// Helpers
// ---------------------------------------------------------------------------
__device__ __forceinline__ float ex2_approx(float x) {
    float r;
    asm("ex2.approx.f32 %0, %1;" : "=f"(r) : "f"(x));
    return r;
}
__device__ __forceinline__ float softplusf(float x) {
    return fmaxf(x, 0.f) + log1pf(__expf(-fabsf(x)));
}
__device__ __forceinline__ float siluf(float x) {
    return x / (1.f + __expf(-x));
}
__device__ __forceinline__ int refl(int v) {
    return v < 0 ? -v : (v > 31 ? 62 - v : v);
}
__device__ __forceinline__ uint32_t smem_u32(const void* p) {
    uint32_t a;
    asm("{ .reg .u64 t; cvta.to.shared.u64 t, %1; cvt.u32.u64 %0, t; }"
        : "=r"(a) : "l"(p));
    return a;
}
__device__ __forceinline__ void mma16816(float* d, const uint32_t* a,
                                          const uint32_t* b) {
    asm volatile(
        "mma.sync.aligned.m16n8k16.row.col.f32.bf16.bf16.f32 "
        "{%0,%1,%2,%3}, {%4,%5,%6,%7}, {%8,%9}, {%0,%1,%2,%3};"
        : "+f"(d[0]), "+f"(d[1]), "+f"(d[2]), "+f"(d[3])
        : "r"(a[0]), "r"(a[1]), "r"(a[2]), "r"(a[3]), "r"(b[0]), "r"(b[1]));
}
__device__ __forceinline__ void cp16(uint32_t s, const void* g) {
    asm volatile("cp.async.cg.shared.global [%0], [%1], 16;"
                 :: "r"(s), "l"(g) : "memory");
}
__device__ __forceinline__ void ldsm_x4(uint32_t* r, uint32_t addr) {
    asm volatile(
        "ldmatrix.sync.aligned.m8n8.x4.shared.b16 {%0,%1,%2,%3}, [%4];"
        : "=r"(r[0]), "=r"(r[1]), "=r"(r[2]), "=r"(r[3]) : "r"(addr));
}

// ---------------------------------------------------------------------------
// 0) Weight transpose + bf16 convert: wt[n][k] = bf16(w[k][n])
// ---------------------------------------------------------------------------
__global__ __launch_bounds__(256) void convert_wT(
    const float* __restrict__ w, __nv_bfloat16* __restrict__ wt, int K, int N)
{
    __shared__ float tile[32][33];
    int nb = blockIdx.x * 32, kb = blockIdx.y * 32;
    int tx = threadIdx.x, ty = threadIdx.y;
#pragma unroll
    for (int i = 0; i < 4; i++)
        tile[ty + i * 8][tx] = w[(size_t)(kb + ty + i * 8) * N + nb + tx];
    __syncthreads();
#pragma unroll
    for (int i = 0; i < 4; i++)
        wt[(size_t)(nb + ty + i * 8) * K + kb + tx] =
            __float2bfloat16(tile[tx][ty + i * 8]);
}

// ---------------------------------------------------------------------------
// 1) LayerNorm: warp per token, also emits channel-mean image g_xg
// ---------------------------------------------------------------------------
__global__ __launch_bounds__(256) void ln_kernel(
    const float* __restrict__ x, const float* __restrict__ gam,
    const float* __restrict__ bet, float* __restrict__ xn,
    float* __restrict__ xgm)
{
    int warp = threadIdx.x >> 5, lane = threadIdx.x & 31;
    int r = blockIdx.x * 8 + warp;
    const float4* xp = (const float4*)(x + (size_t)r * DIM);
    float4 v[3];
    float s = 0.f, s2 = 0.f;
#pragma unroll
    for (int i = 0; i < 3; i++) {
        v[i] = xp[lane + 32 * i];
        s  += v[i].x + v[i].y + v[i].z + v[i].w;
        s2 += v[i].x * v[i].x + v[i].y * v[i].y + v[i].z * v[i].z + v[i].w * v[i].w;
    }
#pragma unroll
    for (int o = 16; o; o >>= 1) {
        s  += __shfl_xor_sync(0xffffffffu, s,  o);
        s2 += __shfl_xor_sync(0xffffffffu, s2, o);
    }
    float mu   = s * (1.f / DIM);
    float var  = s2 * (1.f / DIM) - mu * mu;
    float rstd = rsqrtf(var + 1e-5f);

    float xs = 0.f;
    float4* op = (float4*)(xn + (size_t)r * DIM);
    const float4* gp = (const float4*)gam;
    const float4* bp = (const float4*)bet;
#pragma unroll
    for (int i = 0; i < 3; i++) {
        float4 g4 = gp[lane + 32 * i];
        float4 b4 = bp[lane + 32 * i];
        float4 o4;
        o4.x = (v[i].x - mu) * rstd * g4.x + b4.x;
        o4.y = (v[i].y - mu) * rstd * g4.y + b4.y;
        o4.z = (v[i].z - mu) * rstd * g4.z + b4.z;
        o4.w = (v[i].w - mu) * rstd * g4.w + b4.w;
        xs += o4.x + o4.y + o4.z + o4.w;
        op[lane + 32 * i] = o4;
    }
#pragma unroll
    for (int o = 16; o; o >>= 1) xs += __shfl_xor_sync(0xffffffffu, xs, o);
    if (lane == 0) xgm[r] = xs * (1.f / DIM);
}

// ---------------------------------------------------------------------------
// 2) Direction selection
// ---------------------------------------------------------------------------
__global__ __launch_bounds__(1024) void dir_kernel(
    const float* __restrict__ xg,
    const float* __restrict__ w1, const float* __restrict__ b1,
    const float* __restrict__ w2, const float* __restrict__ b2,
    int* __restrict__ isvert)
{
    __shared__ float s[1024];
    __shared__ float sred[4 * 32];
    __shared__ float s4[4];
    int b = blockIdx.x, t = threadIdx.x;
    s[t] = xg[b * 1024 + t];
    __syncthreads();

    int i = t >> 5, j = t & 31;
    const float inv = 1.0f / 1.0625f;

    float sf = (i + 0.5f) * 1.0625f - 0.5f;
    int x0 = (int)floorf(sf) - 1;
    int jm = refl(j - 1), jp = refl(j + 1);
    float gh = 0.f, ws = 0.f;
#pragma unroll
    for (int dx = 0; dx < 4; ++dx) {
        int xx = x0 + dx;
        if (xx < 0 || xx > 33) continue;
        float w = 1.0f - fabsf(sf - (float)xx) * inv;
        if (w <= 0.f) continue;
        int rr = refl(xx - 1);
        gh += w * fabsf(s[rr * 32 + jp] - s[rr * 32 + jm]);
        ws += w;
    }
    gh /= ws;

    float sfj = (j + 0.5f) * 1.0625f - 0.5f;
    int y0 = (int)floorf(sfj) - 1;
    int im = refl(i - 1), ip = refl(i + 1);
    float gv = 0.f; ws = 0.f;
#pragma unroll
    for (int dx = 0; dx < 4; ++dx) {
        int xx = y0 + dx;
        if (xx < 0 || xx > 33) continue;
        float w = 1.0f - fabsf(sfj - (float)xx) * inv;
        if (w <= 0.f) continue;
        int cc = refl(xx - 1);
        gv += w * fabsf(s[ip * 32 + cc] - s[im * 32 + cc]);
        ws += w;
    }
    gv /= ws;

    float gd = 0.5f * (gh + gv);
    float ga = fabsf(gh - gv);
    float cw = ((i == 0 || i == 31) ? 2.f : 3.f) * ((j == 0 || j == 31) ? 2.f : 3.f);
    float v0 = gh * cw, v1 = gv * cw, v2 = gd * cw, v3 = ga * cw;
#pragma unroll
    for (int o = 16; o; o >>= 1) {
        v0 += __shfl_xor_sync(0xffffffffu, v0, o);
        v1 += __shfl_xor_sync(0xffffffffu, v1, o);
        v2 += __shfl_xor_sync(0xffffffffu, v2, o);
        v3 += __shfl_xor_sync(0xffffffffu, v3, o);
    }
    int wi = t >> 5, ln = t & 31;
    if (ln == 0) {
        sred[0 * 32 + wi] = v0; sred[1 * 32 + wi] = v1;
        sred[2 * 32 + wi] = v2; sred[3 * 32 + wi] = v3;
    }
    __syncthreads();
    if (t < 4) {
        float a = 0.f;
        for (int w = 0; w < 32; w++) a += sred[t * 32 + w];
        s4[t] = a * (1.0f / (9.0f * 1024.0f));
    }
    __syncthreads();
    if (t == 0) {
        float sc0 = s4[0], sc1 = s4[1], sc2 = s4[2], sc3 = s4[3];
        float lg[4] = {b2[0], b2[1], b2[2], b2[3]};
        for (int jj = 0; jj < 32; jj++) {
            float h = b1[jj] + sc0 * w1[0 * 32 + jj] + sc1 * w1[1 * 32 + jj]
                             + sc2 * w1[2 * 32 + jj] + sc3 * w1[3 * 32 + jj];
            h = fmaxf(h, 0.f);
            lg[0] += h * w2[jj * 4 + 0];
            lg[1] += h * w2[jj * 4 + 1];
            lg[2] += h * w2[jj * 4 + 2];
            lg[3] += h * w2[jj * 4 + 3];
        }
        int bi = 0; float bv = lg[0];
        for (int m = 1; m < 4; m++) if (lg[m] > bv) { bv = lg[m]; bi = m; }
        isvert[b] = (bi == 1) ? 1 : 0;
    }
}

// ---------------------------------------------------------------------------
// 3) Gather (optional transpose) -> bf16 sequence
// ---------------------------------------------------------------------------
__global__ __launch_bounds__(256) void gather_kernel(
    const float* __restrict__ xn, const int* __restrict__ isv,
    __nv_bfloat16* __restrict__ seqb)
{
    int idx = blockIdx.x * 256 + threadIdx.x;
    int c4 = idx % 96;
    int r  = idx / 96;
    int b = r >> 10, t = r & 1023;
    int src = isv[b] ? (((t & 31) << 5) | (t >> 5)) : t;
    float4 v = ((const float4*)xn)[(size_t)((b << 10) | src) * 96 + c4];
    __nv_bfloat162 lo = __floats2bfloat162_rn(v.x, v.y);
    __nv_bfloat162 hi = __floats2bfloat162_rn(v.z, v.w);
    uint2 o;
    o.x = *(uint32_t*)&lo;
    o.y = *(uint32_t*)&hi;
    ((uint2*)seqb)[(size_t)r * 96 + c4] = o;
}

// ---------------------------------------------------------------------------
// 4) bf16 mma.sync GEMM with cp.async staging + ldmatrix fragments.
//    C[M,N] = A[M,K] @ Bt[N,K]^T, fp32 accum.
//    Tile 128x128x32, double buffered. MODE: 0 plain, 1 bias+softplus, 2 +res.
// ---------------------------------------------------------------------------
template <int MODE>
__global__ __launch_bounds__(256) void gemm_bf16(
    const __nv_bfloat16* __restrict__ A,
    const __nv_bfloat16* __restrict__ Bt,
    float* __restrict__ C, int N, int K,
    const float* __restrict__ bias, const float* __restrict__ res)
{
    __shared__ __nv_bfloat16 sA[2][128 * 32];
    __shared__ __nv_bfloat16 sB[2][128 * 32];
    int tid  = threadIdx.x;
    int warp = tid >> 5, lane = tid & 31;
    int wm = (warp >> 1) * 32;   // 4 warps along M
    int wn = (warp & 1) * 64;    // 2 warps along N

    const __nv_bfloat16* Ag = A  + (size_t)(blockIdx.y * 128) * K;
    const __nv_bfloat16* Bg = Bt + (size_t)(blockIdx.x * 128) * K;
    uint32_t sA0 = smem_u32(sA), sB0 = smem_u32(sB);

    float acc[2][8][4];
#pragma unroll
    for (int i = 0; i < 2; i++)
#pragma unroll
        for (int j = 0; j < 8; j++)
#pragma unroll
            for (int q = 0; q < 4; q++) acc[i][j][q] = 0.f;

    const int NCH = K >> 5;  // K chunks of 32

    // tile loader: 8KB per operand per buffer; 512 x 16B chunks; 2 per thread
#define LOAD_TILE(buf, k0)                                                    \
    do {                                                                      \
        _Pragma("unroll")                                                     \
        for (int i = 0; i < 2; i++) {                                         \
            int idx = tid + i * 256;                                          \
            int r = idx >> 2, c16 = idx & 3;                                  \
            uint32_t o  = r * 64 + c16 * 16;                                  \
            uint32_t sw = o ^ (((o >> 6) & 7) << 4);                          \
            cp16(sA0 + (buf) * 8192 + sw, Ag + (size_t)r * K + (k0) + c16 * 8); \
            cp16(sB0 + (buf) * 8192 + sw, Bg + (size_t)r * K + (k0) + c16 * 8); \
        }                                                                     \
        asm volatile("cp.async.commit_group;" ::: "memory");                  \
    } while (0)

    LOAD_TILE(0, 0);
    LOAD_TILE(1, 32);

    for (int c = 0; c < NCH; ++c) {
        if (c + 1 < NCH)
            asm volatile("cp.async.wait_group 1;" ::: "memory");
        else
            asm volatile("cp.async.wait_group 0;" ::: "memory");
        __syncthreads();
        int buf = c & 1;
        uint32_t ab = sA0 + buf * 8192;
        uint32_t bb = sB0 + buf * 8192;
        int rsel = lane & 15;
        int kadd = (lane >> 4) << 3;   // 0 or 8 elems
#pragma unroll
        for (int s = 0; s < 2; s++) {
            int ko = s * 16;
            uint32_t af[2][4], bq[4][4];
#pragma unroll
            for (int i = 0; i < 2; i++) {
                uint32_t o  = (uint32_t)(wm + i * 16 + rsel) * 64 + (ko + kadd) * 2;
                uint32_t sw = o ^ (((o >> 6) & 7) << 4);
                ldsm_x4(af[i], ab + sw);
            }
#pragma unroll
            for (int jj = 0; jj < 4; jj++) {
                uint32_t o  = (uint32_t)(wn + jj * 16 + rsel) * 64 + (ko + kadd) * 2;
                uint32_t sw = o ^ (((o >> 6) & 7) << 4);
                ldsm_x4(bq[jj], bb + sw);
            }
#pragma unroll
            for (int i = 0; i < 2; i++) {
#pragma unroll
                for (int jj = 0; jj < 4; jj++) {
                    uint32_t b0[2] = { bq[jj][0], bq[jj][2] };
                    uint32_t b1[2] = { bq[jj][1], bq[jj][3] };
                    mma16816(acc[i][2 * jj],     af[i], b0);
                    mma16816(acc[i][2 * jj + 1], af[i], b1);
                }
            }
        }
        if (c + 2 < NCH) {
            __syncthreads();
            LOAD_TILE(buf, (c + 2) * 32);
        }
    }
#undef LOAD_TILE

    // epilogue
#pragma unroll
    for (int i = 0; i < 2; i++) {
        int row0 = blockIdx.y * 128 + wm + i * 16 + (lane >> 2);
#pragma unroll
        for (int j = 0; j < 8; j++) {
            int col = blockIdx.x * 128 + wn + j * 8 + (lane & 3) * 2;
#pragma unroll
            for (int h = 0; h < 2; h++) {
                int r = row0 + h * 8;
                float2 v = make_float2(acc[i][j][h * 2], acc[i][j][h * 2 + 1]);
                if (MODE == 1) {
                    v.x = softplusf(v.x + bias[col]);
                    v.y = softplusf(v.y + bias[col + 1]);
                } else if (MODE == 2) {
                    float2 rr = *(const float2*)(res + (size_t)r * N + col);
                    v.x += rr.x; v.y += rr.y;
                }
                *(float2*)(C + (size_t)r * N + col) = v;
            }
        }
    }
}

// ---------------------------------------------------------------------------
// 5) Depthwise conv (k=3) + SiLU -> xc (fp32) and xcb (bf16)
// ---------------------------------------------------------------------------
__global__ __launch_bounds__(256) void conv_silu_kernel(
    const float* __restrict__ xz, const float* __restrict__ w,
    const float* __restrict__ cb, float* __restrict__ xc,
    __nv_bfloat16* __restrict__ xcb)
{
    int idx = blockIdx.x * 256 + threadIdx.x;
    int d4 = idx % 192;
    int bt = idx / 192;
    int t  = bt & 1023;
    int d  = d4 * 4;
    const float* base = xz + (size_t)bt * XZW + d;
    float4 c  = *(const float4*)base;
    float4 p  = (t > 0)    ? *(const float4*)(base - XZW) : make_float4(0, 0, 0, 0);
    float4 nx = (t < 1023) ? *(const float4*)(base + XZW) : make_float4(0, 0, 0, 0);
    float4 o;
    o.x = p.x * w[(d + 0) * 3 + 0] + c.x * w[(d + 0) * 3 + 1] + nx.x * w[(d + 0) * 3 + 2] + cb[d + 0];
    o.y = p.y * w[(d + 1) * 3 + 0] + c.y * w[(d + 1) * 3 + 1] + nx.y * w[(d + 1) * 3 + 2] + cb[d + 1];
    o.z = p.z * w[(d + 2) * 3 + 0] + c.z * w[(d + 2) * 3 + 1] + nx.z * w[(d + 2) * 3 + 2] + cb[d + 2];
    o.w = p.w * w[(d + 3) * 3 + 0] + c.w * w[(d + 3) * 3 + 1] + nx.w * w[(d + 3) * 3 + 2] + cb[d + 3];
    o.x = siluf(o.x); o.y = siluf(o.y); o.z = siluf(o.z); o.w = siluf(o.w);
    *(float4*)(xc + (size_t)bt * DI + d) = o;
    __nv_bfloat162 p0 = __floats2bfloat162_rn(o.x, o.y);
    __nv_bfloat162 p1 = __floats2bfloat162_rn(o.z, o.w);
    uint2 ob; ob.x = *(uint32_t*)&p0; ob.y = *(uint32_t*)&p1;
    *(uint2*)(xcb + (size_t)bt * DI + d) = ob;
}

// ---------------------------------------------------------------------------
// 6) x_proj (smem staged)
// ---------------------------------------------------------------------------
__global__ __launch_bounds__(256) void xproj_kernel(
    const float* __restrict__ xc, const float* __restrict__ w,
    float* __restrict__ bcout)
{
    __shared__ float srow[8][DI];
    int warp = threadIdx.x >> 5, lane = threadIdx.x & 31;
    int row = blockIdx.x * 8 + warp;
    const float4* a = (const float4*)(xc + (size_t)row * DI);
    float4* sp = (float4*)srow[warp];
#pragma unroll
    for (int i = 0; i < 6; i++) sp[lane + 32 * i] = a[lane + 32 * i];
    __syncwarp();
    float acc = 0.f;
#pragma unroll 4
    for (int k = 0; k < DI; k += 4) {
        float4 av = *(const float4*)&srow[warp][k];
        acc = fmaf(av.x, w[(k + 0) * 32 + lane], acc);
        acc = fmaf(av.y, w[(k + 1) * 32 + lane], acc);
        acc = fmaf(av.z, w[(k + 2) * 32 + lane], acc);
        acc = fmaf(av.w, w[(k + 3) * 32 + lane], acc);
    }
    bcout[(size_t)row * 32 + lane] = acc;
}

// ---------------------------------------------------------------------------
// 7a) Chunked scan pass 1
// ---------------------------------------------------------------------------
__global__ __launch_bounds__(128) void scan_chunk1(
    const float* __restrict__ delta, const float* __restrict__ xc,
    const float* __restrict__ bc, const float* __restrict__ A_log,
    float* __restrict__ Pout, float* __restrict__ Qout)
{
    int b = blockIdx.y, c = blockIdx.z;
    int tid = threadIdx.x;
    int dloc = tid >> 2, nq = tid & 3;
    int d = blockIdx.x * 32 + dloc;

    const float L2E = 1.44269504f;
    float4 al = *(const float4*)(A_log + (size_t)d * DS + nq * 4);
    float a0 = -__expf(al.x) * L2E;
    float a1 = -__expf(al.y) * L2E;
    float a2 = -__expf(al.z) * L2E;
    float a3 = -__expf(al.w) * L2E;

    int t0 = c * TC;
    const float* dp  = delta + (size_t)(b * 1024 + t0) * DI + d;
    const float* xp  = xc    + (size_t)(b * 1024 + t0) * DI + d;
    const float* bcp = bc    + (size_t)(b * 1024 + t0) * 32 + nq * 4;

    float q0 = 0.f, q1 = 0.f, q2 = 0.f, q3 = 0.f, S = 0.f;
#pragma unroll 4
    for (int t = 0; t < TC; ++t) {
        float de = dp[(size_t)t * DI];
        float xv = xp[(size_t)t * DI];
        float4 Bv = *(const float4*)(bcp + (size_t)t * 32);
        float dx = de * xv;
        float e0 = ex2_approx(de * a0);
        float e1 = ex2_approx(de * a1);
        float e2 = ex2_approx(de * a2);
        float e3 = ex2_approx(de * a3);
        q0 = fmaf(e0, q0, dx * Bv.x);
        q1 = fmaf(e1, q1, dx * Bv.y);
        q2 = fmaf(e2, q2, dx * Bv.z);
        q3 = fmaf(e3, q3, dx * Bv.w);
        S += de;
    }
    size_t idx = (size_t)c * CH_STRIDE + ((size_t)(b * DI + d)) * DS + nq * 4;
    *(float4*)(Pout + idx) = make_float4(ex2_approx(a0 * S), ex2_approx(a1 * S),
                                         ex2_approx(a2 * S), ex2_approx(a3 * S));
    *(float4*)(Qout + idx) = make_float4(q0, q1, q2, q3);
}

// ---------------------------------------------------------------------------
// 7b) Chunked scan pass 2
// ---------------------------------------------------------------------------
__global__ __launch_bounds__(256) void scan_chunk2(
    const float* __restrict__ P, const float* __restrict__ Q,
    float* __restrict__ H0)
{
    int idx = blockIdx.x * 256 + threadIdx.x;
    float h = 0.f;
#pragma unroll
    for (int c = 0; c < NC; ++c) {
        size_t o = (size_t)c * CH_STRIDE + idx;
        H0[o] = h;
        h = fmaf(P[o], h, Q[o]);
    }
}

// ---------------------------------------------------------------------------
// 7c) Chunked scan pass 3: emit gated y (bf16)
// ---------------------------------------------------------------------------
__global__ __launch_bounds__(128) void scan_chunk3(
    const float* __restrict__ delta, const float* __restrict__ xc,
    const float* __restrict__ bc, const float* __restrict__ xz,
    const float* __restrict__ A_log, const float* __restrict__ Dv,
    const float* __restrict__ H0, __nv_bfloat16* __restrict__ yb)
{
    int b = blockIdx.y, c = blockIdx.z;
    int tid = threadIdx.x;
    int dloc = tid >> 2, nq = tid & 3;
    int d = blockIdx.x * 32 + dloc;

    const float L2E = 1.44269504f;
    float4 al = *(const float4*)(A_log + (size_t)d * DS + nq * 4);
    float a0 = -__expf(al.x) * L2E;
    float a1 = -__expf(al.y) * L2E;
    float a2 = -__expf(al.z) * L2E;
    float a3 = -__expf(al.w) * L2E;
    float Dd = Dv[d];

    size_t sidx = (size_t)c * CH_STRIDE + ((size_t)(b * DI + d)) * DS + nq * 4;
    float4 h4 = *(const float4*)(H0 + sidx);
    float h0 = h4.x, h1 = h4.y, h2 = h4.z, h3 = h4.w;

    int t0 = c * TC;
    const float* dp  = delta + (size_t)(b * 1024 + t0) * DI + d;
    const float* xp  = xc    + (size_t)(b * 1024 + t0) * DI + d;
    const float* bcp = bc    + (size_t)(b * 1024 + t0) * 32 + nq * 4;
    const float* zp  = xz    + (size_t)(b * 1024 + t0) * XZW + DI + d;
    __nv_bfloat16* yp = yb   + (size_t)(b * 1024 + t0) * DI + d;

#pragma unroll 4
    for (int t = 0; t < TC; ++t) {
        float de = dp[(size_t)t * DI];
        float xv = xp[(size_t)t * DI];
        float4 Bv = *(const float4*)(bcp + (size_t)t * 32);
        float4 Cv = *(const float4*)(bcp + (size_t)t * 32 + 16);
        float dx = de * xv;
        float e0 = ex2_approx(de * a0);
        float e1 = ex2_approx(de * a1);
        float e2 = ex2_approx(de * a2);
        float e3 = ex2_approx(de * a3);
        h0 = fmaf(e0, h0, dx * Bv.x);
        h1 = fmaf(e1, h1, dx * Bv.y);
        h2 = fmaf(e2, h2, dx * Bv.z);
        h3 = fmaf(e3, h3, dx * Bv.w);
        float acc = h0 * Cv.x + h1 * Cv.y + h2 * Cv.z + h3 * Cv.w;
        acc += __shfl_xor_sync(0xffffffffu, acc, 1);
        acc += __shfl_xor_sync(0xffffffffu, acc, 2);
        if (nq == 0) {
            float z = zp[(size_t)t * XZW];
            yp[(size_t)t * DI] = __float2bfloat16((acc + Dd * xv) * siluf(z));
        }
    }
}

// ---------------------------------------------------------------------------
// launch
// ---------------------------------------------------------------------------
extern "C" void kernel_launch(void* const* d_in, const int* in_sizes, int n_in,
                              void* d_out, int out_size)
{
    const float* x          = (const float*)d_in[0];
    const float* ln_g       = (const float*)d_in[1];
    const float* ln_b       = (const float*)d_in[2];
    const float* mlp_w1     = (const float*)d_in[3];
    const float* mlp_b1     = (const float*)d_in[4];
    const float* mlp_w2     = (const float*)d_in[5];
    const float* mlp_b2     = (const float*)d_in[6];
    const float* in_proj_w  = (const float*)d_in[7];
    const float* conv_w     = (const float*)d_in[8];
    const float* conv_b     = (const float*)d_in[9];
    const float* x_proj_w   = (const float*)d_in[10];
    const float* dt_w       = (const float*)d_in[11];
    const float* dt_b       = (const float*)d_in[12];
    const float* A_log      = (const float*)d_in[13];
    const float* Dv         = (const float*)d_in[14];
    const float* out_proj_w = (const float*)d_in[15];
    float* out = (float*)d_out;

    float *xn, *xg, *xz, *xc, *delta, *bc, *Pp, *Qp, *H0p;
    __nv_bfloat16 *seqb, *xcb, *yb, *wA, *wD, *wO;
    int* isv;
    cudaGetSymbolAddress((void**)&xn,    g_xn);
    cudaGetSymbolAddress((void**)&xg,    g_xg);
    cudaGetSymbolAddress((void**)&isv,   g_isv);
    cudaGetSymbolAddress((void**)&xz,    g_xz);
    cudaGetSymbolAddress((void**)&xc,    g_xc);
    cudaGetSymbolAddress((void**)&delta, g_delta);
    cudaGetSymbolAddress((void**)&bc,    g_bc);
    cudaGetSymbolAddress((void**)&Pp,    g_P);
    cudaGetSymbolAddress((void**)&Qp,    g_Q);
    cudaGetSymbolAddress((void**)&H0p,   g_h0);
    cudaGetSymbolAddress((void**)&seqb,  g_seqb);
    cudaGetSymbolAddress((void**)&xcb,   g_xcb);
    cudaGetSymbolAddress((void**)&yb,    g_yb);
    cudaGetSymbolAddress((void**)&wA,    g_wA);
    cudaGetSymbolAddress((void**)&wD,    g_wD);
    cudaGetSymbolAddress((void**)&wO,    g_wO);

    // weight transpose + bf16 convert
    convert_wT<<<dim3(XZW / 32, DIM / 32), dim3(32, 8)>>>(in_proj_w, wA, DIM, XZW);
    convert_wT<<<dim3(DI / 32, DI / 32),   dim3(32, 8)>>>(dt_w, wD, DI, DI);
    convert_wT<<<dim3(DIM / 32, DI / 32),  dim3(32, 8)>>>(out_proj_w, wO, DI, DIM);

    // 1. LayerNorm (+ channel-mean image)
    ln_kernel<<<NTOK / 8, 256>>>(x, ln_g, ln_b, xn, xg);
    // 2. direction selection
    dir_kernel<<<BATCH, 1024>>>(xg, mlp_w1, mlp_b1, mlp_w2, mlp_b2, isv);
    // 3. gather (optional transpose) -> bf16
    gather_kernel<<<(NTOK * 96) / 256, 256>>>(xn, isv, seqb);
    // 4. in_proj: xz = seq @ in_proj_w   (8192 x 1536, K=384)
    gemm_bf16<0><<<dim3(XZW / 128, NTOK / 128), 256>>>(
        seqb, wA, xz, XZW, DIM, nullptr, nullptr);
    // 5. depthwise conv + silu
    conv_silu_kernel<<<(NTOK * (DI / 4)) / 256, 256>>>(xz, conv_w, conv_b, xc, xcb);
    // 6. x_proj
    xproj_kernel<<<NTOK / 8, 256>>>(xc, x_proj_w, bc);
    // 7. dt: delta = softplus(xc @ dt_w + dt_b)
    gemm_bf16<1><<<dim3(DI / 128, NTOK / 128), 256>>>(
        xcb, wD, delta, DI, DI, dt_b, nullptr);
    // 8. chunked selective scan
    scan_chunk1<<<dim3(DI / 32, BATCH, NC), 128>>>(delta, xc, bc, A_log, Pp, Qp);
    scan_chunk2<<<CH_STRIDE / 256, 256>>>(Pp, Qp, H0p);
    scan_chunk3<<<dim3(DI / 32, BATCH, NC), 128>>>(delta, xc, bc, xz, A_log, Dv,
                                                   H0p, yb);
    // 9. out_proj + residual
    gemm_bf16<2><<<dim3(DIM / 128, NTOK / 128), 256>>>(
        yb, wO, out, DIM, DI, nullptr, x);
}

// round 6
// speedup vs baseline: 3.9605x; 1.0519x over previous
#include <cuda_runtime.h>
#include <cuda_bf16.h>
#include <math.h>
#include <stdint.h>

// ---------------------------------------------------------------------------
// Problem constants
// ---------------------------------------------------------------------------
#define BATCH   8
#define HW      32
#define L_SEQ   1024
#define DIM     384
#define DI      768
#define DS      16
#define XZW     1536
#define NTOK    (BATCH*L_SEQ)

#define NC      16
#define TC      64
#define CH_STRIDE (BATCH*DI*DS)

// ---------------------------------------------------------------------------
// Scratch
// ---------------------------------------------------------------------------
__device__ float g_xg   [NTOK];
__device__ int   g_isv  [BATCH];
__device__ float g_xch  [NTOK*DI];     // in_proj x-half (fp32)
__device__ float g_bc   [NTOK*2*DS];
__device__ float g_P    [NC*CH_STRIDE];
__device__ float g_Q    [NC*CH_STRIDE];
__device__ float g_h0   [NC*CH_STRIDE];

__device__ __nv_bfloat16 g_zb  [NTOK*DI];   // in_proj z-half (bf16)
__device__ __nv_bfloat16 g_seqb[NTOK*DIM];
__device__ __nv_bfloat16 g_xcb [NTOK*DI];   // conv+silu output (bf16)
__device__ __nv_bfloat16 g_dltb[NTOK*DI];   // softplus(dt) (bf16)
__device__ __nv_bfloat16 g_yb  [NTOK*DI];
__device__ __nv_bfloat16 g_wA  [XZW*DIM];   // in_proj_w^T
__device__ __nv_bfloat16 g_wD  [DI*DI];     // dt_w^T
__device__ __nv_bfloat16 g_wO  [DIM*DI];    // out_proj_w^T

// ---------------------------------------------------------------------------
// Helpers
// ---------------------------------------------------------------------------
__device__ __forceinline__ float ex2_approx(float x) {
    float r;
    asm("ex2.approx.f32 %0, %1;" : "=f"(r) : "f"(x));
    return r;
}
__device__ __forceinline__ float softplusf(float x) {
    return fmaxf(x, 0.f) + log1pf(__expf(-fabsf(x)));
}
__device__ __forceinline__ float siluf(float x) {
    return x / (1.f + __expf(-x));
}
__device__ __forceinline__ int refl(int v) {
    return v < 0 ? -v : (v > 31 ? 62 - v : v);
}
__device__ __forceinline__ uint32_t smem_u32(const void* p) {
    uint32_t a;
    asm("{ .reg .u64 t; cvta.to.shared.u64 t, %1; cvt.u32.u64 %0, t; }"
        : "=r"(a) : "l"(p));
    return a;
}
__device__ __forceinline__ void mma16816(float* d, const uint32_t* a,
                                          const uint32_t* b) {
    asm volatile(
        "mma.sync.aligned.m16n8k16.row.col.f32.bf16.bf16.f32 "
        "{%0,%1,%2,%3}, {%4,%5,%6,%7}, {%8,%9}, {%0,%1,%2,%3};"
        : "+f"(d[0]), "+f"(d[1]), "+f"(d[2]), "+f"(d[3])
        : "r"(a[0]), "r"(a[1]), "r"(a[2]), "r"(a[3]), "r"(b[0]), "r"(b[1]));
}
__device__ __forceinline__ void cp16(uint32_t s, const void* g) {
    asm volatile("cp.async.cg.shared.global [%0], [%1], 16;"
                 :: "r"(s), "l"(g) : "memory");
}
__device__ __forceinline__ void ldsm_x4(uint32_t* r, uint32_t addr) {
    asm volatile(
        "ldmatrix.sync.aligned.m8n8.x4.shared.b16 {%0,%1,%2,%3}, [%4];"
        : "=r"(r[0]), "=r"(r[1]), "=r"(r[2]), "=r"(r[3]) : "r"(addr));
}
__device__ __forceinline__ uint32_t pack_bf16(float a, float b) {
    __nv_bfloat162 p = __floats2bfloat162_rn(a, b);
    return *(uint32_t*)&p;
}

// ---------------------------------------------------------------------------
// 0) Weight transpose + bf16 convert: wt[n][k] = bf16(w[k][n])
// ---------------------------------------------------------------------------
__global__ __launch_bounds__(256) void convert_wT(
    const float* __restrict__ w, __nv_bfloat16* __restrict__ wt, int K, int N)
{
    __shared__ float tile[32][33];
    int nb = blockIdx.x * 32, kb = blockIdx.y * 32;
    int tx = threadIdx.x, ty = threadIdx.y;
#pragma unroll
    for (int i = 0; i < 4; i++)
        tile[ty + i * 8][tx] = w[(size_t)(kb + ty + i * 8) * N + nb + tx];
    __syncthreads();
#pragma unroll
    for (int i = 0; i < 4; i++)
        wt[(size_t)(nb + ty + i * 8) * K + kb + tx] =
            __float2bfloat16(tile[tx][ty + i * 8]);
}

// ---------------------------------------------------------------------------
// 1) ln_xg: warp per token, emits only the channel-mean of the LN output
// ---------------------------------------------------------------------------
__global__ __launch_bounds__(256) void ln_xg_kernel(
    const float* __restrict__ x, const float* __restrict__ gam,
    const float* __restrict__ bet, float* __restrict__ xgm)
{
    int warp = threadIdx.x >> 5, lane = threadIdx.x & 31;
    int r = blockIdx.x * 8 + warp;
    const float4* xp = (const float4*)(x + (size_t)r * DIM);
    float4 v[3];
    float s = 0.f, s2 = 0.f;
#pragma unroll
    for (int i = 0; i < 3; i++) {
        v[i] = xp[lane + 32 * i];
        s  += v[i].x + v[i].y + v[i].z + v[i].w;
        s2 += v[i].x * v[i].x + v[i].y * v[i].y + v[i].z * v[i].z + v[i].w * v[i].w;
    }
#pragma unroll
    for (int o = 16; o; o >>= 1) {
        s  += __shfl_xor_sync(0xffffffffu, s,  o);
        s2 += __shfl_xor_sync(0xffffffffu, s2, o);
    }
    float mu   = s * (1.f / DIM);
    float var  = s2 * (1.f / DIM) - mu * mu;
    float rstd = rsqrtf(var + 1e-5f);

    float xs = 0.f;
    const float4* gp = (const float4*)gam;
    const float4* bp = (const float4*)bet;
#pragma unroll
    for (int i = 0; i < 3; i++) {
        float4 g4 = gp[lane + 32 * i];
        float4 b4 = bp[lane + 32 * i];
        xs += (v[i].x - mu) * rstd * g4.x + b4.x;
        xs += (v[i].y - mu) * rstd * g4.y + b4.y;
        xs += (v[i].z - mu) * rstd * g4.z + b4.z;
        xs += (v[i].w - mu) * rstd * g4.w + b4.w;
    }
#pragma unroll
    for (int o = 16; o; o >>= 1) xs += __shfl_xor_sync(0xffffffffu, xs, o);
    if (lane == 0) xgm[r] = xs * (1.f / DIM);
}

// ---------------------------------------------------------------------------
// 2) Direction selection
// ---------------------------------------------------------------------------
__global__ __launch_bounds__(1024) void dir_kernel(
    const float* __restrict__ xg,
    const float* __restrict__ w1, const float* __restrict__ b1,
    const float* __restrict__ w2, const float* __restrict__ b2,
    int* __restrict__ isvert)
{
    __shared__ float s[1024];
    __shared__ float sred[4 * 32];
    __shared__ float s4[4];
    int b = blockIdx.x, t = threadIdx.x;
    s[t] = xg[b * 1024 + t];
    __syncthreads();

    int i = t >> 5, j = t & 31;
    const float inv = 1.0f / 1.0625f;

    float sf = (i + 0.5f) * 1.0625f - 0.5f;
    int x0 = (int)floorf(sf) - 1;
    int jm = refl(j - 1), jp = refl(j + 1);
    float gh = 0.f, ws = 0.f;
#pragma unroll
    for (int dx = 0; dx < 4; ++dx) {
        int xx = x0 + dx;
        if (xx < 0 || xx > 33) continue;
        float w = 1.0f - fabsf(sf - (float)xx) * inv;
        if (w <= 0.f) continue;
        int rr = refl(xx - 1);
        gh += w * fabsf(s[rr * 32 + jp] - s[rr * 32 + jm]);
        ws += w;
    }
    gh /= ws;

    float sfj = (j + 0.5f) * 1.0625f - 0.5f;
    int y0 = (int)floorf(sfj) - 1;
    int im = refl(i - 1), ip = refl(i + 1);
    float gv = 0.f; ws = 0.f;
#pragma unroll
    for (int dx = 0; dx < 4; ++dx) {
        int xx = y0 + dx;
        if (xx < 0 || xx > 33) continue;
        float w = 1.0f - fabsf(sfj - (float)xx) * inv;
        if (w <= 0.f) continue;
        int cc = refl(xx - 1);
        gv += w * fabsf(s[ip * 32 + cc] - s[im * 32 + cc]);
        ws += w;
    }
    gv /= ws;

    float gd = 0.5f * (gh + gv);
    float ga = fabsf(gh - gv);
    float cw = ((i == 0 || i == 31) ? 2.f : 3.f) * ((j == 0 || j == 31) ? 2.f : 3.f);
    float v0 = gh * cw, v1 = gv * cw, v2 = gd * cw, v3 = ga * cw;
#pragma unroll
    for (int o = 16; o; o >>= 1) {
        v0 += __shfl_xor_sync(0xffffffffu, v0, o);
        v1 += __shfl_xor_sync(0xffffffffu, v1, o);
        v2 += __shfl_xor_sync(0xffffffffu, v2, o);
        v3 += __shfl_xor_sync(0xffffffffu, v3, o);
    }
    int wi = t >> 5, ln = t & 31;
    if (ln == 0) {
        sred[0 * 32 + wi] = v0; sred[1 * 32 + wi] = v1;
        sred[2 * 32 + wi] = v2; sred[3 * 32 + wi] = v3;
    }
    __syncthreads();
    if (t < 4) {
        float a = 0.f;
        for (int w = 0; w < 32; w++) a += sred[t * 32 + w];
        s4[t] = a * (1.0f / (9.0f * 1024.0f));
    }
    __syncthreads();
    if (t == 0) {
        float sc0 = s4[0], sc1 = s4[1], sc2 = s4[2], sc3 = s4[3];
        float lg[4] = {b2[0], b2[1], b2[2], b2[3]};
        for (int jj = 0; jj < 32; jj++) {
            float h = b1[jj] + sc0 * w1[0 * 32 + jj] + sc1 * w1[1 * 32 + jj]
                             + sc2 * w1[2 * 32 + jj] + sc3 * w1[3 * 32 + jj];
            h = fmaxf(h, 0.f);
            lg[0] += h * w2[jj * 4 + 0];
            lg[1] += h * w2[jj * 4 + 1];
            lg[2] += h * w2[jj * 4 + 2];
            lg[3] += h * w2[jj * 4 + 3];
        }
        int bi = 0; float bv = lg[0];
        for (int m = 1; m < 4; m++) if (lg[m] > bv) { bv = lg[m]; bi = m; }
        isvert[b] = (bi == 1) ? 1 : 0;
    }
}

// ---------------------------------------------------------------------------
// 3) gather_ln: warp per OUTPUT token; re-derives LayerNorm from x and
//    writes bf16 sequence (optionally HW-transposed)
// ---------------------------------------------------------------------------
__global__ __launch_bounds__(256) void gather_ln_kernel(
    const float* __restrict__ x, const float* __restrict__ gam,
    const float* __restrict__ bet, const int* __restrict__ isv,
    __nv_bfloat16* __restrict__ seqb)
{
    int warp = threadIdx.x >> 5, lane = threadIdx.x & 31;
    int r = blockIdx.x * 8 + warp;
    int b = r >> 10, t = r & 1023;
    int src = isv[b] ? (((t & 31) << 5) | (t >> 5)) : t;
    const float4* xp = (const float4*)(x + (size_t)((b << 10) | src) * DIM);
    float4 v[3];
    float s = 0.f, s2 = 0.f;
#pragma unroll
    for (int i = 0; i < 3; i++) {
        v[i] = xp[lane + 32 * i];
        s  += v[i].x + v[i].y + v[i].z + v[i].w;
        s2 += v[i].x * v[i].x + v[i].y * v[i].y + v[i].z * v[i].z + v[i].w * v[i].w;
    }
#pragma unroll
    for (int o = 16; o; o >>= 1) {
        s  += __shfl_xor_sync(0xffffffffu, s,  o);
        s2 += __shfl_xor_sync(0xffffffffu, s2, o);
    }
    float mu   = s * (1.f / DIM);
    float var  = s2 * (1.f / DIM) - mu * mu;
    float rstd = rsqrtf(var + 1e-5f);

    const float4* gp = (const float4*)gam;
    const float4* bp = (const float4*)bet;
    uint2* op = (uint2*)(seqb + (size_t)r * DIM);
#pragma unroll
    for (int i = 0; i < 3; i++) {
        float4 g4 = gp[lane + 32 * i];
        float4 b4 = bp[lane + 32 * i];
        float ox = (v[i].x - mu) * rstd * g4.x + b4.x;
        float oy = (v[i].y - mu) * rstd * g4.y + b4.y;
        float oz = (v[i].z - mu) * rstd * g4.z + b4.z;
        float ow = (v[i].w - mu) * rstd * g4.w + b4.w;
        uint2 o;
        o.x = pack_bf16(ox, oy);
        o.y = pack_bf16(oz, ow);
        op[lane + 32 * i] = o;
    }
}

// ---------------------------------------------------------------------------
// 4) bf16 mma.sync GEMM (cp.async + ldmatrix). Tile 128x128x32, 2-stage.
//    MODE 1: bias+softplus -> bf16 out (C cast to bf16*)
//    MODE 2: residual-add  -> fp32
//    MODE 3: split writer: col<DI -> fp32 xch, col>=DI -> bf16 zb
// ---------------------------------------------------------------------------
template <int MODE>
__global__ __launch_bounds__(256) void gemm_bf16(
    const __nv_bfloat16* __restrict__ A,
    const __nv_bfloat16* __restrict__ Bt,
    void* __restrict__ Cv, int N, int K,
    const float* __restrict__ bias, const float* __restrict__ res,
    __nv_bfloat16* __restrict__ zb)
{
    __shared__ __nv_bfloat16 sA[2][128 * 32];
    __shared__ __nv_bfloat16 sB[2][128 * 32];
    int tid  = threadIdx.x;
    int warp = tid >> 5, lane = tid & 31;
    int wm = (warp >> 1) * 32;
    int wn = (warp & 1) * 64;

    const __nv_bfloat16* Ag = A  + (size_t)(blockIdx.y * 128) * K;
    const __nv_bfloat16* Bg = Bt + (size_t)(blockIdx.x * 128) * K;
    uint32_t sA0 = smem_u32(sA), sB0 = smem_u32(sB);

    float acc[2][8][4];
#pragma unroll
    for (int i = 0; i < 2; i++)
#pragma unroll
        for (int j = 0; j < 8; j++)
#pragma unroll
            for (int q = 0; q < 4; q++) acc[i][j][q] = 0.f;

    const int NCH = K >> 5;

#define LOAD_TILE(buf, k0)                                                    \
    do {                                                                      \
        _Pragma("unroll")                                                     \
        for (int i = 0; i < 2; i++) {                                         \
            int idx = tid + i * 256;                                          \
            int r = idx >> 2, c16 = idx & 3;                                  \
            uint32_t o  = r * 64 + c16 * 16;                                  \
            uint32_t sw = o ^ (((o >> 6) & 7) << 4);                          \
            cp16(sA0 + (buf) * 8192 + sw, Ag + (size_t)r * K + (k0) + c16 * 8); \
            cp16(sB0 + (buf) * 8192 + sw, Bg + (size_t)r * K + (k0) + c16 * 8); \
        }                                                                     \
        asm volatile("cp.async.commit_group;" ::: "memory");                  \
    } while (0)

    LOAD_TILE(0, 0);
    LOAD_TILE(1, 32);

    for (int c = 0; c < NCH; ++c) {
        if (c + 1 < NCH)
            asm volatile("cp.async.wait_group 1;" ::: "memory");
        else
            asm volatile("cp.async.wait_group 0;" ::: "memory");
        __syncthreads();
        int buf = c & 1;
        uint32_t ab = sA0 + buf * 8192;
        uint32_t bb = sB0 + buf * 8192;
        int rsel = lane & 15;
        int kadd = (lane >> 4) << 3;
#pragma unroll
        for (int s = 0; s < 2; s++) {
            int ko = s * 16;
            uint32_t af[2][4], bq[4][4];
#pragma unroll
            for (int i = 0; i < 2; i++) {
                uint32_t o  = (uint32_t)(wm + i * 16 + rsel) * 64 + (ko + kadd) * 2;
                uint32_t sw = o ^ (((o >> 6) & 7) << 4);
                ldsm_x4(af[i], ab + sw);
            }
#pragma unroll
            for (int jj = 0; jj < 4; jj++) {
                uint32_t o  = (uint32_t)(wn + jj * 16 + rsel) * 64 + (ko + kadd) * 2;
                uint32_t sw = o ^ (((o >> 6) & 7) << 4);
                ldsm_x4(bq[jj], bb + sw);
            }
#pragma unroll
            for (int i = 0; i < 2; i++) {
#pragma unroll
                for (int jj = 0; jj < 4; jj++) {
                    uint32_t b0[2] = { bq[jj][0], bq[jj][2] };
                    uint32_t b1[2] = { bq[jj][1], bq[jj][3] };
                    mma16816(acc[i][2 * jj],     af[i], b0);
                    mma16816(acc[i][2 * jj + 1], af[i], b1);
                }
            }
        }
        if (c + 2 < NCH) {
            __syncthreads();
            LOAD_TILE(buf, (c + 2) * 32);
        }
    }
#undef LOAD_TILE

#pragma unroll
    for (int i = 0; i < 2; i++) {
        int row0 = blockIdx.y * 128 + wm + i * 16 + (lane >> 2);
#pragma unroll
        for (int j = 0; j < 8; j++) {
            int col = blockIdx.x * 128 + wn + j * 8 + (lane & 3) * 2;
#pragma unroll
            for (int h = 0; h < 2; h++) {
                int r = row0 + h * 8;
                float2 v = make_float2(acc[i][j][h * 2], acc[i][j][h * 2 + 1]);
                if (MODE == 1) {
                    v.x = softplusf(v.x + bias[col]);
                    v.y = softplusf(v.y + bias[col + 1]);
                    __nv_bfloat16* Db = (__nv_bfloat16*)Cv;
                    *(uint32_t*)(Db + (size_t)r * N + col) = pack_bf16(v.x, v.y);
                } else if (MODE == 2) {
                    float* C = (float*)Cv;
                    float2 rr = *(const float2*)(res + (size_t)r * N + col);
                    v.x += rr.x; v.y += rr.y;
                    *(float2*)(C + (size_t)r * N + col) = v;
                } else if (MODE == 3) {
                    if (col < DI) {
                        float* C = (float*)Cv;
                        *(float2*)(C + (size_t)r * DI + col) = v;
                    } else {
                        *(uint32_t*)(zb + (size_t)r * DI + col - DI) =
                            pack_bf16(v.x, v.y);
                    }
                } else {
                    float* C = (float*)Cv;
                    *(float2*)(C + (size_t)r * N + col) = v;
                }
            }
        }
    }
}

// ---------------------------------------------------------------------------
// 5) Fused depthwise conv (k=3) + SiLU + x_proj. Warp per token.
//    Reads xch (fp32, stride DI), writes xcb (bf16) and bc.
// ---------------------------------------------------------------------------
__global__ __launch_bounds__(256) void conv_xproj_kernel(
    const float* __restrict__ xch, const float* __restrict__ w,
    const float* __restrict__ cb, const float* __restrict__ wx,
    __nv_bfloat16* __restrict__ xcb, float* __restrict__ bcout)
{
    __shared__ float srow[8][DI];
    int warp = threadIdx.x >> 5, lane = threadIdx.x & 31;
    int r = blockIdx.x * 8 + warp;
    int t = r & 1023;

    const float* base = xch + (size_t)r * DI;
    uint2* xout = (uint2*)(xcb + (size_t)r * DI);
#pragma unroll
    for (int i = 0; i < 6; i++) {
        int c4 = lane + 32 * i;
        int d = c4 * 4;
        float4 cc = *(const float4*)(base + d);
        float4 pp = (t > 0)    ? *(const float4*)(base - DI + d) : make_float4(0, 0, 0, 0);
        float4 nn = (t < 1023) ? *(const float4*)(base + DI + d) : make_float4(0, 0, 0, 0);
        float4 o;
        o.x = pp.x * w[(d + 0) * 3] + cc.x * w[(d + 0) * 3 + 1] + nn.x * w[(d + 0) * 3 + 2] + cb[d + 0];
        o.y = pp.y * w[(d + 1) * 3] + cc.y * w[(d + 1) * 3 + 1] + nn.y * w[(d + 1) * 3 + 2] + cb[d + 1];
        o.z = pp.z * w[(d + 2) * 3] + cc.z * w[(d + 2) * 3 + 1] + nn.z * w[(d + 2) * 3 + 2] + cb[d + 2];
        o.w = pp.w * w[(d + 3) * 3] + cc.w * w[(d + 3) * 3 + 1] + nn.w * w[(d + 3) * 3 + 2] + cb[d + 3];
        o.x = siluf(o.x); o.y = siluf(o.y); o.z = siluf(o.z); o.w = siluf(o.w);
        *(float4*)&srow[warp][d] = o;
        uint2 ob; ob.x = pack_bf16(o.x, o.y); ob.y = pack_bf16(o.z, o.w);
        xout[c4] = ob;
    }
    __syncwarp();
    float acc = 0.f;
#pragma unroll 4
    for (int k = 0; k < DI; k += 4) {
        float4 av = *(const float4*)&srow[warp][k];
        acc = fmaf(av.x, wx[(k + 0) * 32 + lane], acc);
        acc = fmaf(av.y, wx[(k + 1) * 32 + lane], acc);
        acc = fmaf(av.z, wx[(k + 2) * 32 + lane], acc);
        acc = fmaf(av.w, wx[(k + 3) * 32 + lane], acc);
    }
    bcout[(size_t)r * 32 + lane] = acc;
}

// ---------------------------------------------------------------------------
// 6a) Chunked scan pass 1 (bf16 delta/xc inputs)
// ---------------------------------------------------------------------------
__global__ __launch_bounds__(128) void scan_chunk1(
    const __nv_bfloat16* __restrict__ dltb, const __nv_bfloat16* __restrict__ xcb,
    const float* __restrict__ bc, const float* __restrict__ A_log,
    float* __restrict__ Pout, float* __restrict__ Qout)
{
    int b = blockIdx.y, c = blockIdx.z;
    int tid = threadIdx.x;
    int dloc = tid >> 2, nq = tid & 3;
    int d = blockIdx.x * 32 + dloc;

    const float L2E = 1.44269504f;
    float4 al = *(const float4*)(A_log + (size_t)d * DS + nq * 4);
    float a0 = -__expf(al.x) * L2E;
    float a1 = -__expf(al.y) * L2E;
    float a2 = -__expf(al.z) * L2E;
    float a3 = -__expf(al.w) * L2E;

    int t0 = c * TC;
    const __nv_bfloat16* dp = dltb + (size_t)(b * 1024 + t0) * DI + d;
    const __nv_bfloat16* xp = xcb  + (size_t)(b * 1024 + t0) * DI + d;
    const float* bcp = bc + (size_t)(b * 1024 + t0) * 32 + nq * 4;

    float q0 = 0.f, q1 = 0.f, q2 = 0.f, q3 = 0.f, S = 0.f;
#pragma unroll 4
    for (int t = 0; t < TC; ++t) {
        float de = __bfloat162float(dp[(size_t)t * DI]);
        float xv = __bfloat162float(xp[(size_t)t * DI]);
        float4 Bv = *(const float4*)(bcp + (size_t)t * 32);
        float dx = de * xv;
        float e0 = ex2_approx(de * a0);
        float e1 = ex2_approx(de * a1);
        float e2 = ex2_approx(de * a2);
        float e3 = ex2_approx(de * a3);
        q0 = fmaf(e0, q0, dx * Bv.x);
        q1 = fmaf(e1, q1, dx * Bv.y);
        q2 = fmaf(e2, q2, dx * Bv.z);
        q3 = fmaf(e3, q3, dx * Bv.w);
        S += de;
    }
    size_t idx = (size_t)c * CH_STRIDE + ((size_t)(b * DI + d)) * DS + nq * 4;
    *(float4*)(Pout + idx) = make_float4(ex2_approx(a0 * S), ex2_approx(a1 * S),
                                         ex2_approx(a2 * S), ex2_approx(a3 * S));
    *(float4*)(Qout + idx) = make_float4(q0, q1, q2, q3);
}

// ---------------------------------------------------------------------------
// 6b) Chunked scan pass 2
// ---------------------------------------------------------------------------
__global__ __launch_bounds__(256) void scan_chunk2(
    const float* __restrict__ P, const float* __restrict__ Q,
    float* __restrict__ H0)
{
    int idx = blockIdx.x * 256 + threadIdx.x;
    float h = 0.f;
#pragma unroll
    for (int c = 0; c < NC; ++c) {
        size_t o = (size_t)c * CH_STRIDE + idx;
        H0[o] = h;
        h = fmaf(P[o], h, Q[o]);
    }
}

// ---------------------------------------------------------------------------
// 6c) Chunked scan pass 3: emit gated y (bf16)
// ---------------------------------------------------------------------------
__global__ __launch_bounds__(128) void scan_chunk3(
    const __nv_bfloat16* __restrict__ dltb, const __nv_bfloat16* __restrict__ xcb,
    const float* __restrict__ bc, const __nv_bfloat16* __restrict__ zb,
    const float* __restrict__ A_log, const float* __restrict__ Dv,
    const float* __restrict__ H0, __nv_bfloat16* __restrict__ yb)
{
    int b = blockIdx.y, c = blockIdx.z;
    int tid = threadIdx.x;
    int dloc = tid >> 2, nq = tid & 3;
    int d = blockIdx.x * 32 + dloc;

    const float L2E = 1.44269504f;
    float4 al = *(const float4*)(A_log + (size_t)d * DS + nq * 4);
    float a0 = -__expf(al.x) * L2E;
    float a1 = -__expf(al.y) * L2E;
    float a2 = -__expf(al.z) * L2E;
    float a3 = -__expf(al.w) * L2E;
    float Dd = Dv[d];

    size_t sidx = (size_t)c * CH_STRIDE + ((size_t)(b * DI + d)) * DS + nq * 4;
    float4 h4 = *(const float4*)(H0 + sidx);
    float h0 = h4.x, h1 = h4.y, h2 = h4.z, h3 = h4.w;

    int t0 = c * TC;
    const __nv_bfloat16* dp = dltb + (size_t)(b * 1024 + t0) * DI + d;
    const __nv_bfloat16* xp = xcb  + (size_t)(b * 1024 + t0) * DI + d;
    const float* bcp = bc + (size_t)(b * 1024 + t0) * 32 + nq * 4;
    const __nv_bfloat16* zp = zb + (size_t)(b * 1024 + t0) * DI + d;
    __nv_bfloat16* yp = yb + (size_t)(b * 1024 + t0) * DI + d;

#pragma unroll 4
    for (int t = 0; t < TC; ++t) {
        float de = __bfloat162float(dp[(size_t)t * DI]);
        float xv = __bfloat162float(xp[(size_t)t * DI]);
        float4 Bv = *(const float4*)(bcp + (size_t)t * 32);
        float4 Cvv = *(const float4*)(bcp + (size_t)t * 32 + 16);
        float dx = de * xv;
        float e0 = ex2_approx(de * a0);
        float e1 = ex2_approx(de * a1);
        float e2 = ex2_approx(de * a2);
        float e3 = ex2_approx(de * a3);
        h0 = fmaf(e0, h0, dx * Bv.x);
        h1 = fmaf(e1, h1, dx * Bv.y);
        h2 = fmaf(e2, h2, dx * Bv.z);
        h3 = fmaf(e3, h3, dx * Bv.w);
        float acc = h0 * Cvv.x + h1 * Cvv.y + h2 * Cvv.z + h3 * Cvv.w;
        acc += __shfl_xor_sync(0xffffffffu, acc, 1);
        acc += __shfl_xor_sync(0xffffffffu, acc, 2);
        if (nq == 0) {
            float z = __bfloat162float(zp[(size_t)t * DI]);
            yp[(size_t)t * DI] = __float2bfloat16((acc + Dd * xv) * siluf(z));
        }
    }
}

// ---------------------------------------------------------------------------
// launch
// ---------------------------------------------------------------------------
extern "C" void kernel_launch(void* const* d_in, const int* in_sizes, int n_in,
                              void* d_out, int out_size)
{
    const float* x          = (const float*)d_in[0];
    const float* ln_g       = (const float*)d_in[1];
    const float* ln_b       = (const float*)d_in[2];
    const float* mlp_w1     = (const float*)d_in[3];
    const float* mlp_b1     = (const float*)d_in[4];
    const float* mlp_w2     = (const float*)d_in[5];
    const float* mlp_b2     = (const float*)d_in[6];
    const float* in_proj_w  = (const float*)d_in[7];
    const float* conv_w     = (const float*)d_in[8];
    const float* conv_b     = (const float*)d_in[9];
    const float* x_proj_w   = (const float*)d_in[10];
    const float* dt_w       = (const float*)d_in[11];
    const float* dt_b       = (const float*)d_in[12];
    const float* A_log      = (const float*)d_in[13];
    const float* Dv         = (const float*)d_in[14];
    const float* out_proj_w = (const float*)d_in[15];
    float* out = (float*)d_out;

    float *xg, *xch, *bc, *Pp, *Qp, *H0p;
    __nv_bfloat16 *seqb, *xcb, *yb, *wA, *wD, *wO, *zbp, *dltb;
    int* isv;
    cudaGetSymbolAddress((void**)&xg,    g_xg);
    cudaGetSymbolAddress((void**)&isv,   g_isv);
    cudaGetSymbolAddress((void**)&xch,   g_xch);
    cudaGetSymbolAddress((void**)&bc,    g_bc);
    cudaGetSymbolAddress((void**)&Pp,    g_P);
    cudaGetSymbolAddress((void**)&Qp,    g_Q);
    cudaGetSymbolAddress((void**)&H0p,   g_h0);
    cudaGetSymbolAddress((void**)&seqb,  g_seqb);
    cudaGetSymbolAddress((void**)&xcb,   g_xcb);
    cudaGetSymbolAddress((void**)&yb,    g_yb);
    cudaGetSymbolAddress((void**)&wA,    g_wA);
    cudaGetSymbolAddress((void**)&wD,    g_wD);
    cudaGetSymbolAddress((void**)&wO,    g_wO);
    cudaGetSymbolAddress((void**)&zbp,   g_zb);
    cudaGetSymbolAddress((void**)&dltb,  g_dltb);

    // weight transpose + bf16 convert
    convert_wT<<<dim3(XZW / 32, DIM / 32), dim3(32, 8)>>>(in_proj_w, wA, DIM, XZW);
    convert_wT<<<dim3(DI / 32, DI / 32),   dim3(32, 8)>>>(dt_w, wD, DI, DI);
    convert_wT<<<dim3(DIM / 32, DI / 32),  dim3(32, 8)>>>(out_proj_w, wO, DI, DIM);

    // 1. channel-mean of LN output (for direction MLP)
    ln_xg_kernel<<<NTOK / 8, 256>>>(x, ln_g, ln_b, xg);
    // 2. direction selection
    dir_kernel<<<BATCH, 1024>>>(xg, mlp_w1, mlp_b1, mlp_w2, mlp_b2, isv);
    // 3. fused gather + LayerNorm -> bf16
    gather_ln_kernel<<<NTOK / 8, 256>>>(x, ln_g, ln_b, isv, seqb);
    // 4. in_proj (split output: x-half fp32, z-half bf16)
    gemm_bf16<3><<<dim3(XZW / 128, NTOK / 128), 256>>>(
        seqb, wA, xch, XZW, DIM, nullptr, nullptr, zbp);
    // 5. fused depthwise conv + silu + x_proj
    conv_xproj_kernel<<<NTOK / 8, 256>>>(xch, conv_w, conv_b, x_proj_w, xcb, bc);
    // 6. dt: delta = softplus(xc @ dt_w + dt_b) -> bf16
    gemm_bf16<1><<<dim3(DI / 128, NTOK / 128), 256>>>(
        xcb, wD, dltb, DI, DI, dt_b, nullptr, nullptr);
    // 7. chunked selective scan
    scan_chunk1<<<dim3(DI / 32, BATCH, NC), 128>>>(dltb, xcb, bc, A_log, Pp, Qp);
    scan_chunk2<<<CH_STRIDE / 256, 256>>>(Pp, Qp, H0p);
    scan_chunk3<<<dim3(DI / 32, BATCH, NC), 128>>>(dltb, xcb, bc, zbp, A_log, Dv,
                                                   H0p, yb);
    // 8. out_proj + residual
    gemm_bf16<2><<<dim3(DIM / 128, NTOK / 128), 256>>>(
        yb, wO, out, DIM, DI, nullptr, x, nullptr);
}